// round 2
// baseline (speedup 1.0000x reference)
#include <cuda_runtime.h>
#include <math.h>

// Problem constants
#define NB 2
#define NS 2048
#define ND 1024
#define NH 16
#define NDH 64
#define NF 4096
#define NM (NB*NS)          // 4096 rows total

// ---------------- scratch (device globals: allocation-free rule) ----------------
__device__ float g_h  [(size_t)NM*ND];          // LN output (reused for LN2)
__device__ float g_q  [(size_t)NM*ND];
__device__ float g_k  [(size_t)NM*ND];
__device__ float g_v  [(size_t)NM*ND];
__device__ float g_ctx[(size_t)NM*ND];
__device__ float g_ffn[(size_t)NM*NF];
__device__ float g_sc [(size_t)NB*NH*NS*NS];    // 537 MB score/attn buffer

// ---------------- LayerNorm: one block per row, 256 threads ----------------
__global__ void ln_kernel(const float* __restrict__ x,
                          const float* __restrict__ g,
                          const float* __restrict__ b,
                          float* __restrict__ out) {
    __shared__ float red[8];
    const int row = blockIdx.x;
    const int t = threadIdx.x;
    const float4 v = reinterpret_cast<const float4*>(x + (size_t)row * ND)[t];

    float s = v.x + v.y + v.z + v.w;
    #pragma unroll
    for (int o = 16; o; o >>= 1) s += __shfl_xor_sync(0xffffffffu, s, o);
    if ((t & 31) == 0) red[t >> 5] = s;
    __syncthreads();
    float tot = 0.f;
    #pragma unroll
    for (int i = 0; i < 8; i++) tot += red[i];
    const float mean = tot * (1.0f / ND);
    __syncthreads();

    const float dx = v.x - mean, dy = v.y - mean, dz = v.z - mean, dw = v.w - mean;
    float ss = dx*dx + dy*dy + dz*dz + dw*dw;
    #pragma unroll
    for (int o = 16; o; o >>= 1) ss += __shfl_xor_sync(0xffffffffu, ss, o);
    if ((t & 31) == 0) red[t >> 5] = ss;
    __syncthreads();
    float var = 0.f;
    #pragma unroll
    for (int i = 0; i < 8; i++) var += red[i];
    var *= (1.0f / ND);
    const float inv = rsqrtf(var + 1e-5f);

    const float4 gg = reinterpret_cast<const float4*>(g)[t];
    const float4 bb = reinterpret_cast<const float4*>(b)[t];
    float4 o4;
    o4.x = dx * inv * gg.x + bb.x;
    o4.y = dy * inv * gg.y + bb.y;
    o4.z = dz * inv * gg.z + bb.z;
    o4.w = dw * inv * gg.w + bb.w;
    reinterpret_cast<float4*>(out + (size_t)row * ND)[t] = o4;
}

// ---------------- General SGEMM: C = epi(A[M,K] @ W[K,N]) ----------------
// epilogue: v = acc + bias[n]; if(relu) v=max(v,0); v*=scale; if(res) v+=res[m,n]
// Requires M%128==0, N%128==0, K%16==0 (true for all uses here).
__global__ __launch_bounds__(256)
void sgemm_kernel(int M, int N, int K,
                  const float* __restrict__ A, const float* __restrict__ Bm,
                  const float* __restrict__ bias, const float* __restrict__ res,
                  float* __restrict__ C, float scale, int relu) {
    const int BM = 128, BN = 128, BK = 16;
    __shared__ float As[BK][BM];   // A stored transposed: As[k][m]
    __shared__ float Bs[BK][BN];

    const int bm = blockIdx.y * BM;
    const int bn = blockIdx.x * BN;
    const int tid = threadIdx.x;
    const int tx = tid & 15;   // 16 cols of threads
    const int ty = tid >> 4;   // 16 rows of threads

    float acc[8][8];
    #pragma unroll
    for (int i = 0; i < 8; i++)
        #pragma unroll
        for (int j = 0; j < 8; j++) acc[i][j] = 0.f;

    for (int k0 = 0; k0 < K; k0 += BK) {
        #pragma unroll
        for (int i = 0; i < 2; i++) {
            const int f = tid + i * 256;            // 512 float4 per tile
            const int ar = f >> 2, ac = (f & 3) << 2;
            const float4 a4 = *reinterpret_cast<const float4*>(
                &A[(size_t)(bm + ar) * K + k0 + ac]);
            As[ac + 0][ar] = a4.x;
            As[ac + 1][ar] = a4.y;
            As[ac + 2][ar] = a4.z;
            As[ac + 3][ar] = a4.w;
            const int br = f >> 5, bc = (f & 31) << 2;
            *reinterpret_cast<float4*>(&Bs[br][bc]) =
                *reinterpret_cast<const float4*>(&Bm[(size_t)(k0 + br) * N + bn + bc]);
        }
        __syncthreads();

        #pragma unroll
        for (int k = 0; k < BK; k++) {
            float ar[8], br[8];
            *reinterpret_cast<float4*>(&ar[0]) = *reinterpret_cast<const float4*>(&As[k][ty * 8]);
            *reinterpret_cast<float4*>(&ar[4]) = *reinterpret_cast<const float4*>(&As[k][ty * 8 + 4]);
            *reinterpret_cast<float4*>(&br[0]) = *reinterpret_cast<const float4*>(&Bs[k][tx * 8]);
            *reinterpret_cast<float4*>(&br[4]) = *reinterpret_cast<const float4*>(&Bs[k][tx * 8 + 4]);
            #pragma unroll
            for (int i = 0; i < 8; i++)
                #pragma unroll
                for (int j = 0; j < 8; j++)
                    acc[i][j] = fmaf(ar[i], br[j], acc[i][j]);
        }
        __syncthreads();
    }

    #pragma unroll
    for (int i = 0; i < 8; i++) {
        const int row = bm + ty * 8 + i;
        #pragma unroll
        for (int j = 0; j < 8; j += 4) {
            const int col = bn + tx * 8 + j;
            float4 v;
            v.x = acc[i][j + 0] + bias[col + 0];
            v.y = acc[i][j + 1] + bias[col + 1];
            v.z = acc[i][j + 2] + bias[col + 2];
            v.w = acc[i][j + 3] + bias[col + 3];
            if (relu) {
                v.x = fmaxf(v.x, 0.f); v.y = fmaxf(v.y, 0.f);
                v.z = fmaxf(v.z, 0.f); v.w = fmaxf(v.w, 0.f);
            }
            v.x *= scale; v.y *= scale; v.z *= scale; v.w *= scale;
            if (res) {
                const float4 r = *reinterpret_cast<const float4*>(&res[(size_t)row * N + col]);
                v.x += r.x; v.y += r.y; v.z += r.z; v.w += r.w;
            }
            *reinterpret_cast<float4*>(&C[(size_t)row * N + col]) = v;
        }
    }
}

// ---------------- scores[bh, s, t] = sum_d q[b,s,h,d] * k[b,t,h,d]  (+mask) ----------------
// grid: (NS/64, NS/64, NB*NH), 256 threads, 64x64 tile, K = 64
__global__ __launch_bounds__(256)
void score_kernel(const float* __restrict__ q, const float* __restrict__ k,
                  const unsigned char* __restrict__ mask, float* __restrict__ sc) {
    __shared__ float Qs[NDH][64 + 4];   // [k][row]
    __shared__ float Ks[NDH][64 + 4];   // [k][col]
    const int bh = blockIdx.z;
    const int b = bh >> 4, h = bh & 15;
    const int s0 = blockIdx.y * 64, t0 = blockIdx.x * 64;
    const int tid = threadIdx.x;
    const int tx = tid & 15, ty = tid >> 4;

    const float* qb = q + ((size_t)b * NS) * ND + h * NDH;
    const float* kb = k + ((size_t)b * NS) * ND + h * NDH;

    #pragma unroll
    for (int i = 0; i < 4; i++) {
        const int f = tid + i * 256;           // 1024 float4 per tile
        const int row = f >> 4, kc = (f & 15) << 2;
        const float4 a = *reinterpret_cast<const float4*>(&qb[(size_t)(s0 + row) * ND + kc]);
        Qs[kc + 0][row] = a.x; Qs[kc + 1][row] = a.y;
        Qs[kc + 2][row] = a.z; Qs[kc + 3][row] = a.w;
        const float4 c = *reinterpret_cast<const float4*>(&kb[(size_t)(t0 + row) * ND + kc]);
        Ks[kc + 0][row] = c.x; Ks[kc + 1][row] = c.y;
        Ks[kc + 2][row] = c.z; Ks[kc + 3][row] = c.w;
    }
    __syncthreads();

    float acc[4][4];
    #pragma unroll
    for (int i = 0; i < 4; i++)
        #pragma unroll
        for (int j = 0; j < 4; j++) acc[i][j] = 0.f;

    #pragma unroll 8
    for (int kk = 0; kk < NDH; kk++) {
        float ar[4], br[4];
        *reinterpret_cast<float4*>(ar) = *reinterpret_cast<const float4*>(&Qs[kk][ty * 4]);
        *reinterpret_cast<float4*>(br) = *reinterpret_cast<const float4*>(&Ks[kk][tx * 4]);
        #pragma unroll
        for (int i = 0; i < 4; i++)
            #pragma unroll
            for (int j = 0; j < 4; j++)
                acc[i][j] = fmaf(ar[i], br[j], acc[i][j]);
    }

    float* out = sc + (size_t)bh * NS * NS;
    #pragma unroll
    for (int i = 0; i < 4; i++) {
        const int s = s0 + ty * 4 + i;
        const int t = t0 + tx * 4;
        const uchar4 m4 = *reinterpret_cast<const uchar4*>(
            &mask[((size_t)b * NS + s) * NS + t]);
        float4 v;
        v.x = m4.x ? -1e18f : acc[i][0];
        v.y = m4.y ? -1e18f : acc[i][1];
        v.z = m4.z ? -1e18f : acc[i][2];
        v.w = m4.w ? -1e18f : acc[i][3];
        *reinterpret_cast<float4*>(&out[(size_t)s * NS + t]) = v;
    }
}

// ---------------- row softmax over 2048, one block per row ----------------
__global__ void softmax_kernel(float* __restrict__ sc) {
    __shared__ float red[8];
    const size_t row = blockIdx.x;
    float4* p = reinterpret_cast<float4*>(sc + row * NS);
    const int t = threadIdx.x;
    float4 v0 = p[t], v1 = p[t + 256];

    float m = fmaxf(fmaxf(fmaxf(v0.x, v0.y), fmaxf(v0.z, v0.w)),
                    fmaxf(fmaxf(v1.x, v1.y), fmaxf(v1.z, v1.w)));
    #pragma unroll
    for (int o = 16; o; o >>= 1) m = fmaxf(m, __shfl_xor_sync(0xffffffffu, m, o));
    if ((t & 31) == 0) red[t >> 5] = m;
    __syncthreads();
    float rm = red[0];
    #pragma unroll
    for (int i = 1; i < 8; i++) rm = fmaxf(rm, red[i]);
    __syncthreads();

    v0.x = __expf(v0.x - rm); v0.y = __expf(v0.y - rm);
    v0.z = __expf(v0.z - rm); v0.w = __expf(v0.w - rm);
    v1.x = __expf(v1.x - rm); v1.y = __expf(v1.y - rm);
    v1.z = __expf(v1.z - rm); v1.w = __expf(v1.w - rm);

    float s = v0.x + v0.y + v0.z + v0.w + v1.x + v1.y + v1.z + v1.w;
    #pragma unroll
    for (int o = 16; o; o >>= 1) s += __shfl_xor_sync(0xffffffffu, s, o);
    if ((t & 31) == 0) red[t >> 5] = s;
    __syncthreads();
    float tot = 0.f;
    #pragma unroll
    for (int i = 0; i < 8; i++) tot += red[i];
    const float inv = 1.0f / tot;

    v0.x *= inv; v0.y *= inv; v0.z *= inv; v0.w *= inv;
    v1.x *= inv; v1.y *= inv; v1.z *= inv; v1.w *= inv;
    p[t] = v0; p[t + 256] = v1;
}

// ---------------- ctx[b, s, h*64+c] = sum_t attn[bh, s, t] * v[b,t,h,c] ----------------
// grid: (NS/64, NB*NH), 256 threads, 64x64 output tile, K = 2048 in BK=32 steps
__global__ __launch_bounds__(256)
void ctx_kernel(const float* __restrict__ attn, const float* __restrict__ v,
                float* __restrict__ ctx) {
    __shared__ float As[32][64 + 4];   // [k][row] (attn tile transposed)
    __shared__ float Vs[32][64 + 4];   // [k][col]
    const int bh = blockIdx.y;
    const int b = bh >> 4, h = bh & 15;
    const int s0 = blockIdx.x * 64;
    const int tid = threadIdx.x;
    const int tx = tid & 15, ty = tid >> 4;

    const float* Ab = attn + (size_t)bh * NS * NS;
    const float* Vb = v + ((size_t)b * NS) * ND + h * NDH;

    float acc[4][4];
    #pragma unroll
    for (int i = 0; i < 4; i++)
        #pragma unroll
        for (int j = 0; j < 4; j++) acc[i][j] = 0.f;

    for (int k0 = 0; k0 < NS; k0 += 32) {
        #pragma unroll
        for (int i = 0; i < 2; i++) {
            const int f = tid + i * 256;          // 512 float4 per tile
            const int ar = f >> 3, ac = (f & 7) << 2;   // 64 rows x 32 k
            const float4 a = *reinterpret_cast<const float4*>(
                &Ab[(size_t)(s0 + ar) * NS + k0 + ac]);
            As[ac + 0][ar] = a.x; As[ac + 1][ar] = a.y;
            As[ac + 2][ar] = a.z; As[ac + 3][ar] = a.w;
            const int vr = f >> 4, vc = (f & 15) << 2;  // 32 rows x 64 cols
            *reinterpret_cast<float4*>(&Vs[vr][vc]) =
                *reinterpret_cast<const float4*>(&Vb[(size_t)(k0 + vr) * ND + vc]);
        }
        __syncthreads();
        #pragma unroll
        for (int k = 0; k < 32; k++) {
            float ar[4], br[4];
            *reinterpret_cast<float4*>(ar) = *reinterpret_cast<const float4*>(&As[k][ty * 4]);
            *reinterpret_cast<float4*>(br) = *reinterpret_cast<const float4*>(&Vs[k][tx * 4]);
            #pragma unroll
            for (int i = 0; i < 4; i++)
                #pragma unroll
                for (int j = 0; j < 4; j++)
                    acc[i][j] = fmaf(ar[i], br[j], acc[i][j]);
        }
        __syncthreads();
    }

    #pragma unroll
    for (int i = 0; i < 4; i++) {
        const int s = s0 + ty * 4 + i;
        float4 o;
        o.x = acc[i][0]; o.y = acc[i][1]; o.z = acc[i][2]; o.w = acc[i][3];
        *reinterpret_cast<float4*>(
            &ctx[((size_t)b * NS + s) * ND + h * NDH + tx * 4]) = o;
    }
}

// ---------------- host launch ----------------
extern "C" void kernel_launch(void* const* d_in, const int* in_sizes, int n_in,
                              void* d_out, int out_size) {
    const float* x   = (const float*)d_in[0];
    const unsigned char* mask = (const unsigned char*)d_in[1];
    const float* Wq  = (const float*)d_in[2];
    const float* bq  = (const float*)d_in[3];
    const float* Wk  = (const float*)d_in[4];
    const float* bk  = (const float*)d_in[5];
    const float* Wv  = (const float*)d_in[6];
    const float* bv  = (const float*)d_in[7];
    const float* Wo  = (const float*)d_in[8];
    const float* bo  = (const float*)d_in[9];
    const float* ln1g = (const float*)d_in[10];
    const float* ln1b = (const float*)d_in[11];
    const float* ln2g = (const float*)d_in[12];
    const float* ln2b = (const float*)d_in[13];
    const float* W1  = (const float*)d_in[14];
    const float* b1  = (const float*)d_in[15];
    const float* W2  = (const float*)d_in[16];
    const float* b2  = (const float*)d_in[17];
    float* out = (float*)d_out;

    float *h, *q, *k, *v, *ctx, *ffn, *sc;
    cudaGetSymbolAddress((void**)&h,   g_h);
    cudaGetSymbolAddress((void**)&q,   g_q);
    cudaGetSymbolAddress((void**)&k,   g_k);
    cudaGetSymbolAddress((void**)&v,   g_v);
    cudaGetSymbolAddress((void**)&ctx, g_ctx);
    cudaGetSymbolAddress((void**)&ffn, g_ffn);
    cudaGetSymbolAddress((void**)&sc,  g_sc);

    const float qscale = 0.125f;   // 1/sqrt(64)

    // 1. LN1
    ln_kernel<<<NM, 256>>>(x, ln1g, ln1b, h);
    // 2-4. Q,K,V projections
    sgemm_kernel<<<dim3(ND/128, NM/128), 256>>>(NM, ND, ND, h, Wq, bq, nullptr, q, qscale, 0);
    sgemm_kernel<<<dim3(ND/128, NM/128), 256>>>(NM, ND, ND, h, Wk, bk, nullptr, k, 1.0f, 0);
    sgemm_kernel<<<dim3(ND/128, NM/128), 256>>>(NM, ND, ND, h, Wv, bv, nullptr, v, 1.0f, 0);
    // 5. scores (+mask)
    score_kernel<<<dim3(NS/64, NS/64, NB*NH), 256>>>(q, k, mask, sc);
    // 6. softmax
    softmax_kernel<<<NB*NH*NS, 256>>>(sc);
    // 7. ctx = attn @ V  (written directly in [B,S,D] layout)
    ctx_kernel<<<dim3(NS/64, NB*NH), 256>>>(sc, v, ctx);
    // 8. x1 = x + ctx @ Wo + bo   -> d_out
    sgemm_kernel<<<dim3(ND/128, NM/128), 256>>>(NM, ND, ND, ctx, Wo, bo, x, out, 1.0f, 0);
    // 9. LN2
    ln_kernel<<<NM, 256>>>(out, ln2g, ln2b, h);
    // 10. ffn = relu(h @ W1 + b1)
    sgemm_kernel<<<dim3(NF/128, NM/128), 256>>>(NM, NF, ND, h, W1, b1, nullptr, ffn, 1.0f, 1);
    // 11. out = x1 + ffn @ W2 + b2
    sgemm_kernel<<<dim3(ND/128, NM/128), 256>>>(NM, ND, NF, ffn, W2, b2, out, out, 1.0f, 0);
}

// round 5
// speedup vs baseline: 1.8078x; 1.8078x over previous
#include <cuda_runtime.h>
#include <math.h>
#include <stdint.h>

// Problem constants
#define NB 2
#define NS 2048
#define ND 1024
#define NH 16
#define NDH 64
#define NF 4096
#define NM (NB*NS)          // 4096 rows total

// ---------------- scratch (device globals: allocation-free rule) ----------------
__device__ float g_h  [(size_t)NM*ND];
__device__ float g_q  [(size_t)NM*ND];
__device__ float g_k  [(size_t)NM*ND];
__device__ float g_v  [(size_t)NM*ND];
__device__ float g_ctx[(size_t)NM*ND];
__device__ float g_ffn[(size_t)NM*NF];
__device__ float g_sc [(size_t)NB*NH*NS*NS];    // 537 MB score/attn buffer
// transposed weights [N,K] K-major
__device__ float g_wq[(size_t)ND*ND];
__device__ float g_wk[(size_t)ND*ND];
__device__ float g_wv[(size_t)ND*ND];
__device__ float g_wo[(size_t)ND*ND];
__device__ float g_w1[(size_t)NF*ND];   // W1^T: [F, D]
__device__ float g_w2[(size_t)ND*NF];   // W2^T: [D, F]

// ======================= helpers =======================
__device__ __forceinline__ uint32_t smem_u32(const void* p) {
    uint32_t a;
    asm("{ .reg .u64 t; cvta.to.shared.u64 t, %1; cvt.u32.u64 %0, t; }"
        : "=r"(a) : "l"(p));
    return a;
}

__device__ __forceinline__ uint32_t f2tf32(float f) {
    uint32_t u;
    asm("cvt.rna.tf32.f32 %0, %1;" : "=r"(u) : "f"(f));
    return u;
}

__device__ __forceinline__ void mma_tf32(float* d, const uint32_t* a, const uint32_t* b) {
    asm volatile(
        "mma.sync.aligned.m16n8k8.row.col.f32.tf32.tf32.f32 "
        "{%0,%1,%2,%3}, {%4,%5,%6,%7}, {%8,%9}, {%0,%1,%2,%3};"
        : "+f"(d[0]), "+f"(d[1]), "+f"(d[2]), "+f"(d[3])
        : "r"(a[0]), "r"(a[1]), "r"(a[2]), "r"(a[3]), "r"(b[0]), "r"(b[1]));
}

#define CP_ASYNC16(dst, src) \
    asm volatile("cp.async.cg.shared.global [%0], [%1], 16;" :: "r"(dst), "l"(src))
#define CP_COMMIT() asm volatile("cp.async.commit_group;" ::: "memory")
#define CP_WAIT(n)  asm volatile("cp.async.wait_group %0;" :: "n"(n) : "memory")

// ---------------- transpose: out[c, r] = in[r, c] ----------------
// grid must be (cols/32, rows/32)
__global__ void transpose_kernel(const float* __restrict__ in, float* __restrict__ out,
                                 int rows, int cols) {
    __shared__ float tile[32][33];
    const int c0 = blockIdx.x * 32, r0 = blockIdx.y * 32;
    const int tx = threadIdx.x, ty = threadIdx.y;
    #pragma unroll
    for (int j = 0; j < 32; j += 8)
        tile[ty + j][tx] = in[(size_t)(r0 + ty + j) * cols + c0 + tx];
    __syncthreads();
    #pragma unroll
    for (int j = 0; j < 32; j += 8)
        out[(size_t)(c0 + ty + j) * rows + r0 + tx] = tile[tx][ty + j];
}

// ---------------- LayerNorm ----------------
__global__ void ln_kernel(const float* __restrict__ x,
                          const float* __restrict__ g,
                          const float* __restrict__ b,
                          float* __restrict__ out) {
    __shared__ float red[8];
    const int row = blockIdx.x;
    const int t = threadIdx.x;
    const float4 v = reinterpret_cast<const float4*>(x + (size_t)row * ND)[t];

    float s = v.x + v.y + v.z + v.w;
    #pragma unroll
    for (int o = 16; o; o >>= 1) s += __shfl_xor_sync(0xffffffffu, s, o);
    if ((t & 31) == 0) red[t >> 5] = s;
    __syncthreads();
    float tot = 0.f;
    #pragma unroll
    for (int i = 0; i < 8; i++) tot += red[i];
    const float mean = tot * (1.0f / ND);
    __syncthreads();

    const float dx = v.x - mean, dy = v.y - mean, dz = v.z - mean, dw = v.w - mean;
    float ss = dx*dx + dy*dy + dz*dz + dw*dw;
    #pragma unroll
    for (int o = 16; o; o >>= 1) ss += __shfl_xor_sync(0xffffffffu, ss, o);
    if ((t & 31) == 0) red[t >> 5] = ss;
    __syncthreads();
    float var = 0.f;
    #pragma unroll
    for (int i = 0; i < 8; i++) var += red[i];
    var *= (1.0f / ND);
    const float inv = rsqrtf(var + 1e-5f);

    const float4 gg = reinterpret_cast<const float4*>(g)[t];
    const float4 bb = reinterpret_cast<const float4*>(b)[t];
    float4 o4;
    o4.x = dx * inv * gg.x + bb.x;
    o4.y = dy * inv * gg.y + bb.y;
    o4.z = dz * inv * gg.z + bb.z;
    o4.w = dw * inv * gg.w + bb.w;
    reinterpret_cast<float4*>(out + (size_t)row * ND)[t] = o4;
}

// ================ tf32 mma.sync GEMM: C = epi(A[M,K] @ Wt[N,K]^T) ================
// BM=128, BN=128, BK=32. 8 warps, warp tile 64x32 (4x4 of m16n8k8).
// SMEM: A/B tiles [128][36] padded, double buffered, cp.async pipeline.
#define SROW 36
#define TILE_F (128 * SROW)                     // floats per tile buffer
#define GEMM_SMEM (4 * TILE_F * 4)              // 4 buffers x 18432B = 73728

__global__ __launch_bounds__(256)
void mma_gemm(int N, int K,
              const float* __restrict__ A, const float* __restrict__ Wt,
              const float* __restrict__ bias, const float* __restrict__ res,
              float* __restrict__ C, float scale, int relu) {
    extern __shared__ float sm[];
    float* sAf = sm;                  // [2][128][36]
    float* sBf = sm + 2 * TILE_F;     // [2][128][36]
    const uint32_t sA_u = smem_u32(sAf);
    const uint32_t sB_u = smem_u32(sBf);

    const int tid = threadIdx.x;
    const int wid = tid >> 5, lane = tid & 31;
    const int g = lane >> 2, t = lane & 3;
    const int wm = (wid & 1) * 64;       // warp m offset in tile
    const int wn = (wid >> 1) * 32;      // warp n offset in tile
    const int bm = blockIdx.y * 128;
    const int bn = blockIdx.x * 128;

    // per-thread load coords: 4 float4 per tile per operand
    const int lr = tid >> 3;             // base row 0..31 (+32*i)
    const int lc = (tid & 7) << 2;       // float col 0..28

    float acc[4][4][4];
    #pragma unroll
    for (int mi = 0; mi < 4; mi++)
        #pragma unroll
        for (int ni = 0; ni < 4; ni++)
            #pragma unroll
            for (int j = 0; j < 4; j++) acc[mi][ni][j] = 0.f;

    const int numT = K >> 5;

    // ---- async tile loader ----
    auto load_tile = [&](int tt, int buf) {
        const int k0 = tt * 32;
        #pragma unroll
        for (int i = 0; i < 4; i++) {
            const int r = lr + i * 32;
            const uint32_t off = (uint32_t)(r * SROW + lc) * 4u;
            CP_ASYNC16(sA_u + (uint32_t)buf * (TILE_F * 4) + off,
                       &A[(size_t)(bm + r) * K + k0 + lc]);
            CP_ASYNC16(sB_u + (uint32_t)buf * (TILE_F * 4) + off,
                       &Wt[(size_t)(bn + r) * K + k0 + lc]);
        }
    };

    load_tile(0, 0);
    CP_COMMIT();

    for (int tt = 0; tt < numT; tt++) {
        const int buf = tt & 1;
        if (tt + 1 < numT) {
            load_tile(tt + 1, buf ^ 1);
            CP_COMMIT();
            CP_WAIT(1);
        } else {
            CP_WAIT(0);
        }
        __syncthreads();

        const float* As = sAf + buf * TILE_F;
        const float* Bs = sBf + buf * TILE_F;

        #pragma unroll
        for (int ks = 0; ks < 4; ks++) {
            const int k8 = ks * 8;
            uint32_t af[4][4], bf[4][2];
            #pragma unroll
            for (int mi = 0; mi < 4; mi++) {
                const int r0 = wm + mi * 16 + g;
                af[mi][0] = f2tf32(As[r0 * SROW + k8 + t]);
                af[mi][1] = f2tf32(As[(r0 + 8) * SROW + k8 + t]);
                af[mi][2] = f2tf32(As[r0 * SROW + k8 + t + 4]);
                af[mi][3] = f2tf32(As[(r0 + 8) * SROW + k8 + t + 4]);
            }
            #pragma unroll
            for (int ni = 0; ni < 4; ni++) {
                const int n0 = wn + ni * 8 + g;
                bf[ni][0] = f2tf32(Bs[n0 * SROW + k8 + t]);
                bf[ni][1] = f2tf32(Bs[n0 * SROW + k8 + t + 4]);
            }
            #pragma unroll
            for (int mi = 0; mi < 4; mi++)
                #pragma unroll
                for (int ni = 0; ni < 4; ni++)
                    mma_tf32(acc[mi][ni], af[mi], bf[ni]);
        }
        __syncthreads();
    }

    // ---- epilogue: bias / relu / scale / residual ----
    #pragma unroll
    for (int mi = 0; mi < 4; mi++) {
        const int row0 = bm + wm + mi * 16 + g;
        #pragma unroll
        for (int ni = 0; ni < 4; ni++) {
            const int col = bn + wn + ni * 8 + 2 * t;
            const float2 b2 = *reinterpret_cast<const float2*>(&bias[col]);
            float v0 = acc[mi][ni][0] + b2.x;
            float v1 = acc[mi][ni][1] + b2.y;
            float v2 = acc[mi][ni][2] + b2.x;
            float v3 = acc[mi][ni][3] + b2.y;
            if (relu) {
                v0 = fmaxf(v0, 0.f); v1 = fmaxf(v1, 0.f);
                v2 = fmaxf(v2, 0.f); v3 = fmaxf(v3, 0.f);
            }
            v0 *= scale; v1 *= scale; v2 *= scale; v3 *= scale;
            if (res) {
                const float2 r0 = *reinterpret_cast<const float2*>(
                    &res[(size_t)row0 * N + col]);
                const float2 r1 = *reinterpret_cast<const float2*>(
                    &res[(size_t)(row0 + 8) * N + col]);
                v0 += r0.x; v1 += r0.y; v2 += r1.x; v3 += r1.y;
            }
            float2 o0 = {v0, v1}, o1 = {v2, v3};
            *reinterpret_cast<float2*>(&C[(size_t)row0 * N + col]) = o0;
            *reinterpret_cast<float2*>(&C[(size_t)(row0 + 8) * N + col]) = o1;
        }
    }
}

// ---------------- scores[bh, s, t] = sum_d q.k (+mask) ----------------
__global__ __launch_bounds__(256)
void score_kernel(const float* __restrict__ q, const float* __restrict__ k,
                  const unsigned char* __restrict__ mask, float* __restrict__ sc) {
    __shared__ float Qs[NDH][64 + 4];
    __shared__ float Ks[NDH][64 + 4];
    const int bh = blockIdx.z;
    const int b = bh >> 4, h = bh & 15;
    const int s0 = blockIdx.y * 64, t0 = blockIdx.x * 64;
    const int tid = threadIdx.x;
    const int tx = tid & 15, ty = tid >> 4;

    const float* qb = q + ((size_t)b * NS) * ND + h * NDH;
    const float* kb = k + ((size_t)b * NS) * ND + h * NDH;

    #pragma unroll
    for (int i = 0; i < 4; i++) {
        const int f = tid + i * 256;
        const int row = f >> 4, kc = (f & 15) << 2;
        const float4 a = *reinterpret_cast<const float4*>(&qb[(size_t)(s0 + row) * ND + kc]);
        Qs[kc + 0][row] = a.x; Qs[kc + 1][row] = a.y;
        Qs[kc + 2][row] = a.z; Qs[kc + 3][row] = a.w;
        const float4 c = *reinterpret_cast<const float4*>(&kb[(size_t)(t0 + row) * ND + kc]);
        Ks[kc + 0][row] = c.x; Ks[kc + 1][row] = c.y;
        Ks[kc + 2][row] = c.z; Ks[kc + 3][row] = c.w;
    }
    __syncthreads();

    float acc[4][4];
    #pragma unroll
    for (int i = 0; i < 4; i++)
        #pragma unroll
        for (int j = 0; j < 4; j++) acc[i][j] = 0.f;

    #pragma unroll 8
    for (int kk = 0; kk < NDH; kk++) {
        float ar[4], br[4];
        *reinterpret_cast<float4*>(ar) = *reinterpret_cast<const float4*>(&Qs[kk][ty * 4]);
        *reinterpret_cast<float4*>(br) = *reinterpret_cast<const float4*>(&Ks[kk][tx * 4]);
        #pragma unroll
        for (int i = 0; i < 4; i++)
            #pragma unroll
            for (int j = 0; j < 4; j++)
                acc[i][j] = fmaf(ar[i], br[j], acc[i][j]);
    }

    float* out = sc + (size_t)bh * NS * NS;
    #pragma unroll
    for (int i = 0; i < 4; i++) {
        const int s = s0 + ty * 4 + i;
        const int t = t0 + tx * 4;
        const uchar4 m4 = *reinterpret_cast<const uchar4*>(
            &mask[((size_t)b * NS + s) * NS + t]);
        float4 v;
        v.x = m4.x ? -1e18f : acc[i][0];
        v.y = m4.y ? -1e18f : acc[i][1];
        v.z = m4.z ? -1e18f : acc[i][2];
        v.w = m4.w ? -1e18f : acc[i][3];
        *reinterpret_cast<float4*>(&out[(size_t)s * NS + t]) = v;
    }
}

// ---------------- row softmax over 2048 ----------------
__global__ void softmax_kernel(float* __restrict__ sc) {
    __shared__ float red[8];
    const size_t row = blockIdx.x;
    float4* p = reinterpret_cast<float4*>(sc + row * NS);
    const int t = threadIdx.x;
    float4 v0 = p[t], v1 = p[t + 256];

    float m = fmaxf(fmaxf(fmaxf(v0.x, v0.y), fmaxf(v0.z, v0.w)),
                    fmaxf(fmaxf(v1.x, v1.y), fmaxf(v1.z, v1.w)));
    #pragma unroll
    for (int o = 16; o; o >>= 1) m = fmaxf(m, __shfl_xor_sync(0xffffffffu, m, o));
    if ((t & 31) == 0) red[t >> 5] = m;
    __syncthreads();
    float rm = red[0];
    #pragma unroll
    for (int i = 1; i < 8; i++) rm = fmaxf(rm, red[i]);
    __syncthreads();

    v0.x = __expf(v0.x - rm); v0.y = __expf(v0.y - rm);
    v0.z = __expf(v0.z - rm); v0.w = __expf(v0.w - rm);
    v1.x = __expf(v1.x - rm); v1.y = __expf(v1.y - rm);
    v1.z = __expf(v1.z - rm); v1.w = __expf(v1.w - rm);

    float s = v0.x + v0.y + v0.z + v0.w + v1.x + v1.y + v1.z + v1.w;
    #pragma unroll
    for (int o = 16; o; o >>= 1) s += __shfl_xor_sync(0xffffffffu, s, o);
    if ((t & 31) == 0) red[t >> 5] = s;
    __syncthreads();
    float tot = 0.f;
    #pragma unroll
    for (int i = 0; i < 8; i++) tot += red[i];
    const float inv = 1.0f / tot;

    v0.x *= inv; v0.y *= inv; v0.z *= inv; v0.w *= inv;
    v1.x *= inv; v1.y *= inv; v1.z *= inv; v1.w *= inv;
    p[t] = v0; p[t + 256] = v1;
}

// ---------------- ctx = attn @ V ----------------
__global__ __launch_bounds__(256)
void ctx_kernel(const float* __restrict__ attn, const float* __restrict__ v,
                float* __restrict__ ctx) {
    __shared__ float As[32][64 + 4];
    __shared__ float Vs[32][64 + 4];
    const int bh = blockIdx.y;
    const int b = bh >> 4, h = bh & 15;
    const int s0 = blockIdx.x * 64;
    const int tid = threadIdx.x;
    const int tx = tid & 15, ty = tid >> 4;

    const float* Ab = attn + (size_t)bh * NS * NS;
    const float* Vb = v + ((size_t)b * NS) * ND + h * NDH;

    float acc[4][4];
    #pragma unroll
    for (int i = 0; i < 4; i++)
        #pragma unroll
        for (int j = 0; j < 4; j++) acc[i][j] = 0.f;

    for (int k0 = 0; k0 < NS; k0 += 32) {
        #pragma unroll
        for (int i = 0; i < 2; i++) {
            const int f = tid + i * 256;
            const int ar = f >> 3, ac = (f & 7) << 2;
            const float4 a = *reinterpret_cast<const float4*>(
                &Ab[(size_t)(s0 + ar) * NS + k0 + ac]);
            As[ac + 0][ar] = a.x; As[ac + 1][ar] = a.y;
            As[ac + 2][ar] = a.z; As[ac + 3][ar] = a.w;
            const int vr = f >> 4, vc = (f & 15) << 2;
            *reinterpret_cast<float4*>(&Vs[vr][vc]) =
                *reinterpret_cast<const float4*>(&Vb[(size_t)(k0 + vr) * ND + vc]);
        }
        __syncthreads();
        #pragma unroll
        for (int k = 0; k < 32; k++) {
            float ar[4], br[4];
            *reinterpret_cast<float4*>(ar) = *reinterpret_cast<const float4*>(&As[k][ty * 4]);
            *reinterpret_cast<float4*>(br) = *reinterpret_cast<const float4*>(&Vs[k][tx * 4]);
            #pragma unroll
            for (int i = 0; i < 4; i++)
                #pragma unroll
                for (int j = 0; j < 4; j++)
                    acc[i][j] = fmaf(ar[i], br[j], acc[i][j]);
        }
        __syncthreads();
    }

    #pragma unroll
    for (int i = 0; i < 4; i++) {
        const int s = s0 + ty * 4 + i;
        float4 o;
        o.x = acc[i][0]; o.y = acc[i][1]; o.z = acc[i][2]; o.w = acc[i][3];
        *reinterpret_cast<float4*>(
            &ctx[((size_t)b * NS + s) * ND + h * NDH + tx * 4]) = o;
    }
}

// ---------------- host launch ----------------
extern "C" void kernel_launch(void* const* d_in, const int* in_sizes, int n_in,
                              void* d_out, int out_size) {
    const float* x   = (const float*)d_in[0];
    const unsigned char* mask = (const unsigned char*)d_in[1];
    const float* Wq  = (const float*)d_in[2];
    const float* bq  = (const float*)d_in[3];
    const float* Wk  = (const float*)d_in[4];
    const float* bk  = (const float*)d_in[5];
    const float* Wv  = (const float*)d_in[6];
    const float* bv  = (const float*)d_in[7];
    const float* Wo  = (const float*)d_in[8];
    const float* bo  = (const float*)d_in[9];
    const float* ln1g = (const float*)d_in[10];
    const float* ln1b = (const float*)d_in[11];
    const float* ln2g = (const float*)d_in[12];
    const float* ln2b = (const float*)d_in[13];
    const float* W1  = (const float*)d_in[14];
    const float* b1  = (const float*)d_in[15];
    const float* W2  = (const float*)d_in[16];
    const float* b2  = (const float*)d_in[17];
    float* out = (float*)d_out;

    float *h, *q, *k, *v, *ctx, *ffn, *sc;
    float *wq, *wk, *wv, *wo, *w1, *w2;
    cudaGetSymbolAddress((void**)&h,   g_h);
    cudaGetSymbolAddress((void**)&q,   g_q);
    cudaGetSymbolAddress((void**)&k,   g_k);
    cudaGetSymbolAddress((void**)&v,   g_v);
    cudaGetSymbolAddress((void**)&ctx, g_ctx);
    cudaGetSymbolAddress((void**)&ffn, g_ffn);
    cudaGetSymbolAddress((void**)&sc,  g_sc);
    cudaGetSymbolAddress((void**)&wq,  g_wq);
    cudaGetSymbolAddress((void**)&wk,  g_wk);
    cudaGetSymbolAddress((void**)&wv,  g_wv);
    cudaGetSymbolAddress((void**)&wo,  g_wo);
    cudaGetSymbolAddress((void**)&w1,  g_w1);
    cudaGetSymbolAddress((void**)&w2,  g_w2);

    cudaFuncSetAttribute(mma_gemm, cudaFuncAttributeMaxDynamicSharedMemorySize,
                         GEMM_SMEM);

    const float qscale = 0.125f;   // 1/sqrt(64)
    const dim3 tb(32, 8);

    // 0. weight transposes to [N, K] K-major. grid = (cols/32, rows/32)
    transpose_kernel<<<dim3(ND/32, ND/32), tb>>>(Wq, wq, ND, ND);
    transpose_kernel<<<dim3(ND/32, ND/32), tb>>>(Wk, wk, ND, ND);
    transpose_kernel<<<dim3(ND/32, ND/32), tb>>>(Wv, wv, ND, ND);
    transpose_kernel<<<dim3(ND/32, ND/32), tb>>>(Wo, wo, ND, ND);
    transpose_kernel<<<dim3(NF/32, ND/32), tb>>>(W1, w1, ND, NF);   // W1: [D,F]
    transpose_kernel<<<dim3(ND/32, NF/32), tb>>>(W2, w2, NF, ND);   // W2: [F,D]  (fixed grid)

    // 1. LN1
    ln_kernel<<<NM, 256>>>(x, ln1g, ln1b, h);
    // 2-4. Q,K,V projections (tf32 mma.sync)
    mma_gemm<<<dim3(ND/128, NM/128), 256, GEMM_SMEM>>>(ND, ND, h, wq, bq, nullptr, q, qscale, 0);
    mma_gemm<<<dim3(ND/128, NM/128), 256, GEMM_SMEM>>>(ND, ND, h, wk, bk, nullptr, k, 1.0f, 0);
    mma_gemm<<<dim3(ND/128, NM/128), 256, GEMM_SMEM>>>(ND, ND, h, wv, bv, nullptr, v, 1.0f, 0);
    // 5. scores (+mask)
    score_kernel<<<dim3(NS/64, NS/64, NB*NH), 256>>>(q, k, mask, sc);
    // 6. softmax
    softmax_kernel<<<NB*NH*NS, 256>>>(sc);
    // 7. ctx = attn @ V
    ctx_kernel<<<dim3(NS/64, NB*NH), 256>>>(sc, v, ctx);
    // 8. x1 = x + ctx @ Wo + bo   -> d_out
    mma_gemm<<<dim3(ND/128, NM/128), 256, GEMM_SMEM>>>(ND, ND, ctx, wo, bo, x, out, 1.0f, 0);
    // 9. LN2
    ln_kernel<<<NM, 256>>>(out, ln2g, ln2b, h);
    // 10. ffn = relu(h @ W1 + b1)
    mma_gemm<<<dim3(NF/128, NM/128), 256, GEMM_SMEM>>>(NF, ND, h, w1, b1, nullptr, ffn, 1.0f, 1);
    // 11. out = x1 + ffn @ W2 + b2
    mma_gemm<<<dim3(ND/128, NM/128), 256, GEMM_SMEM>>>(ND, NF, ffn, w2, b2, out, out, 1.0f, 0);
}

// round 6
// speedup vs baseline: 1.8254x; 1.0098x over previous
#include <cuda_runtime.h>
#include <math.h>
#include <stdint.h>

// Problem constants
#define NB 2
#define NS 2048
#define ND 1024
#define NH 16
#define NDH 64
#define NF 4096
#define NM (NB*NS)          // 4096 rows total
#define N3 (3*ND)           // 3072

// ---------------- scratch (device globals: allocation-free rule) ----------------
__device__ float g_h   [(size_t)NM*ND];
__device__ float g_ctx [(size_t)NM*ND];
__device__ float g_ffn [(size_t)NM*NF];
__device__ float g_qkv [(size_t)NM*N3];
__device__ float g_wqkv[(size_t)3*ND*ND];   // [3072,1024] K-major concat of Wq^T,Wk^T,Wv^T
__device__ float g_wo  [(size_t)ND*ND];
__device__ float g_w1  [(size_t)NF*ND];     // W1^T: [F, D]
__device__ float g_w2  [(size_t)ND*NF];     // W2^T: [D, F]
__device__ float g_bqkv[N3];

// ======================= helpers =======================
__device__ __forceinline__ uint32_t smem_u32(const void* p) {
    uint32_t a;
    asm("{ .reg .u64 t; cvta.to.shared.u64 t, %1; cvt.u32.u64 %0, t; }"
        : "=r"(a) : "l"(p));
    return a;
}

__device__ __forceinline__ uint32_t f2tf32(float f) {
    uint32_t u;
    asm("cvt.rna.tf32.f32 %0, %1;" : "=r"(u) : "f"(f));
    return u;
}

__device__ __forceinline__ void mma_tf32(float* d, const uint32_t* a, const uint32_t* b) {
    asm volatile(
        "mma.sync.aligned.m16n8k8.row.col.f32.tf32.tf32.f32 "
        "{%0,%1,%2,%3}, {%4,%5,%6,%7}, {%8,%9}, {%0,%1,%2,%3};"
        : "+f"(d[0]), "+f"(d[1]), "+f"(d[2]), "+f"(d[3])
        : "r"(a[0]), "r"(a[1]), "r"(a[2]), "r"(a[3]), "r"(b[0]), "r"(b[1]));
}

#define CP_ASYNC16(dst, src) \
    asm volatile("cp.async.cg.shared.global [%0], [%1], 16;" :: "r"(dst), "l"(src))
#define CP_COMMIT() asm volatile("cp.async.commit_group;" ::: "memory")
#define CP_WAIT(n)  asm volatile("cp.async.wait_group %0;" :: "n"(n) : "memory")

// ---------------- transpose: out[c, r] = in[r, c]; grid = (cols/32, rows/32) ----------------
__global__ void transpose_kernel(const float* __restrict__ in, float* __restrict__ out,
                                 int rows, int cols) {
    __shared__ float tile[32][33];
    const int c0 = blockIdx.x * 32, r0 = blockIdx.y * 32;
    const int tx = threadIdx.x, ty = threadIdx.y;
    #pragma unroll
    for (int j = 0; j < 32; j += 8)
        tile[ty + j][tx] = in[(size_t)(r0 + ty + j) * cols + c0 + tx];
    __syncthreads();
    #pragma unroll
    for (int j = 0; j < 32; j += 8)
        out[(size_t)(c0 + ty + j) * rows + r0 + tx] = tile[tx][ty + j];
}

// ---------------- concat QKV biases ----------------
__global__ void concat_bias_kernel(const float* __restrict__ bq, const float* __restrict__ bk,
                                   const float* __restrict__ bv, float* __restrict__ out) {
    const int i = blockIdx.x * 256 + threadIdx.x;
    out[i] = (i < ND) ? bq[i] : (i < 2 * ND ? bk[i - ND] : bv[i - 2 * ND]);
}

// ---------------- LayerNorm ----------------
__global__ void ln_kernel(const float* __restrict__ x,
                          const float* __restrict__ g,
                          const float* __restrict__ b,
                          float* __restrict__ out) {
    __shared__ float red[8];
    const int row = blockIdx.x;
    const int t = threadIdx.x;
    const float4 v = reinterpret_cast<const float4*>(x + (size_t)row * ND)[t];

    float s = v.x + v.y + v.z + v.w;
    #pragma unroll
    for (int o = 16; o; o >>= 1) s += __shfl_xor_sync(0xffffffffu, s, o);
    if ((t & 31) == 0) red[t >> 5] = s;
    __syncthreads();
    float tot = 0.f;
    #pragma unroll
    for (int i = 0; i < 8; i++) tot += red[i];
    const float mean = tot * (1.0f / ND);
    __syncthreads();

    const float dx = v.x - mean, dy = v.y - mean, dz = v.z - mean, dw = v.w - mean;
    float ss = dx*dx + dy*dy + dz*dz + dw*dw;
    #pragma unroll
    for (int o = 16; o; o >>= 1) ss += __shfl_xor_sync(0xffffffffu, ss, o);
    if ((t & 31) == 0) red[t >> 5] = ss;
    __syncthreads();
    float var = 0.f;
    #pragma unroll
    for (int i = 0; i < 8; i++) var += red[i];
    var *= (1.0f / ND);
    const float inv = rsqrtf(var + 1e-5f);

    const float4 gg = reinterpret_cast<const float4*>(g)[t];
    const float4 bb = reinterpret_cast<const float4*>(b)[t];
    float4 o4;
    o4.x = dx * inv * gg.x + bb.x;
    o4.y = dy * inv * gg.y + bb.y;
    o4.z = dz * inv * gg.z + bb.z;
    o4.w = dw * inv * gg.w + bb.w;
    reinterpret_cast<float4*>(out + (size_t)row * ND)[t] = o4;
}

// ================ tf32 mma.sync GEMM: C = epi(A[M,K] @ Wt[N,K]^T) ================
#define SROW 36
#define TILE_F (128 * SROW)
#define GEMM_SMEM (4 * TILE_F * 4)

__global__ __launch_bounds__(256)
void mma_gemm(int N, int K,
              const float* __restrict__ A, const float* __restrict__ Wt,
              const float* __restrict__ bias, const float* __restrict__ res,
              float* __restrict__ C, float scale, int relu) {
    extern __shared__ float sm[];
    float* sAf = sm;
    float* sBf = sm + 2 * TILE_F;
    const uint32_t sA_u = smem_u32(sAf);
    const uint32_t sB_u = smem_u32(sBf);

    const int tid = threadIdx.x;
    const int wid = tid >> 5, lane = tid & 31;
    const int g = lane >> 2, t = lane & 3;
    const int wm = (wid & 1) * 64;
    const int wn = (wid >> 1) * 32;
    const int bm = blockIdx.y * 128;
    const int bn = blockIdx.x * 128;

    const int lr = tid >> 3;
    const int lc = (tid & 7) << 2;

    float acc[4][4][4];
    #pragma unroll
    for (int mi = 0; mi < 4; mi++)
        #pragma unroll
        for (int ni = 0; ni < 4; ni++)
            #pragma unroll
            for (int j = 0; j < 4; j++) acc[mi][ni][j] = 0.f;

    const int numT = K >> 5;

    auto load_tile = [&](int tt, int buf) {
        const int k0 = tt * 32;
        #pragma unroll
        for (int i = 0; i < 4; i++) {
            const int r = lr + i * 32;
            const uint32_t off = (uint32_t)(r * SROW + lc) * 4u;
            CP_ASYNC16(sA_u + (uint32_t)buf * (TILE_F * 4) + off,
                       &A[(size_t)(bm + r) * K + k0 + lc]);
            CP_ASYNC16(sB_u + (uint32_t)buf * (TILE_F * 4) + off,
                       &Wt[(size_t)(bn + r) * K + k0 + lc]);
        }
    };

    load_tile(0, 0);
    CP_COMMIT();

    for (int tt = 0; tt < numT; tt++) {
        const int buf = tt & 1;
        if (tt + 1 < numT) {
            load_tile(tt + 1, buf ^ 1);
            CP_COMMIT();
            CP_WAIT(1);
        } else {
            CP_WAIT(0);
        }
        __syncthreads();

        const float* As = sAf + buf * TILE_F;
        const float* Bs = sBf + buf * TILE_F;

        #pragma unroll
        for (int ks = 0; ks < 4; ks++) {
            const int k8 = ks * 8;
            uint32_t af[4][4], bf[4][2];
            #pragma unroll
            for (int mi = 0; mi < 4; mi++) {
                const int r0 = wm + mi * 16 + g;
                af[mi][0] = f2tf32(As[r0 * SROW + k8 + t]);
                af[mi][1] = f2tf32(As[(r0 + 8) * SROW + k8 + t]);
                af[mi][2] = f2tf32(As[r0 * SROW + k8 + t + 4]);
                af[mi][3] = f2tf32(As[(r0 + 8) * SROW + k8 + t + 4]);
            }
            #pragma unroll
            for (int ni = 0; ni < 4; ni++) {
                const int n0 = wn + ni * 8 + g;
                bf[ni][0] = f2tf32(Bs[n0 * SROW + k8 + t]);
                bf[ni][1] = f2tf32(Bs[n0 * SROW + k8 + t + 4]);
            }
            #pragma unroll
            for (int mi = 0; mi < 4; mi++)
                #pragma unroll
                for (int ni = 0; ni < 4; ni++)
                    mma_tf32(acc[mi][ni], af[mi], bf[ni]);
        }
        __syncthreads();
    }

    #pragma unroll
    for (int mi = 0; mi < 4; mi++) {
        const int row0 = bm + wm + mi * 16 + g;
        #pragma unroll
        for (int ni = 0; ni < 4; ni++) {
            const int col = bn + wn + ni * 8 + 2 * t;
            const float2 b2 = *reinterpret_cast<const float2*>(&bias[col]);
            float v0 = acc[mi][ni][0] + b2.x;
            float v1 = acc[mi][ni][1] + b2.y;
            float v2 = acc[mi][ni][2] + b2.x;
            float v3 = acc[mi][ni][3] + b2.y;
            if (relu) {
                v0 = fmaxf(v0, 0.f); v1 = fmaxf(v1, 0.f);
                v2 = fmaxf(v2, 0.f); v3 = fmaxf(v3, 0.f);
            }
            v0 *= scale; v1 *= scale; v2 *= scale; v3 *= scale;
            if (res) {
                const float2 r0 = *reinterpret_cast<const float2*>(
                    &res[(size_t)row0 * N + col]);
                const float2 r1 = *reinterpret_cast<const float2*>(
                    &res[(size_t)(row0 + 8) * N + col]);
                v0 += r0.x; v1 += r0.y; v2 += r1.x; v3 += r1.y;
            }
            float2 o0 = {v0, v1}, o1 = {v2, v3};
            *reinterpret_cast<float2*>(&C[(size_t)row0 * N + col]) = o0;
            *reinterpret_cast<float2*>(&C[(size_t)(row0 + 8) * N + col]) = o1;
        }
    }
}

// ================ Flash attention ================
// grid (NS/128, NB*NH), 256 threads. Q tile 128x64, loop over 16 K/V tiles of 128.
// S = Q K^T (tf32 mma) -> SMEM; online softmax; O += P V (tf32 mma, reg accum).
#define QK_S 68          // Q/K smem row stride (floats)
#define SS_S 132         // S tile row stride
#define VT_S 133         // V^T row stride
#define FL_SMEM ((128*QK_S + 128*QK_S + 64*VT_S + 128*SS_S + 3*128) * 4)

__global__ __launch_bounds__(256)
void flash_kernel(const float* __restrict__ qkv,
                  const unsigned char* __restrict__ mask,
                  float* __restrict__ ctx) {
    extern __shared__ float fs[];
    float* Qs  = fs;                        // [128][68]
    float* Ks  = Qs + 128 * QK_S;           // [128][68]
    float* Vt  = Ks + 128 * QK_S;           // [64][133] (V transposed)
    float* Ss  = Vt + 64 * VT_S;            // [128][132]
    float* m_s = Ss + 128 * SS_S;           // [128]
    float* l_s = m_s + 128;
    float* f_s = l_s + 128;

    const int tid = threadIdx.x;
    const int wid = tid >> 5, lane = tid & 31;
    const int g = lane >> 2, tq = lane & 3;
    const int bh = blockIdx.y;
    const int b = bh >> 4, h = bh & 15;
    const int s0 = blockIdx.x * 128;

    // load Q tile (apply 1/sqrt(dh) here)
    #pragma unroll
    for (int i = 0; i < 8; i++) {
        const int f = tid + i * 256;
        const int r = f >> 4, d4 = (f & 15) << 2;
        const float4 v4 = *reinterpret_cast<const float4*>(
            &qkv[(size_t)(b * NS + s0 + r) * N3 + h * NDH + d4]);
        float* dst = &Qs[r * QK_S + d4];
        dst[0] = v4.x * 0.125f; dst[1] = v4.y * 0.125f;
        dst[2] = v4.z * 0.125f; dst[3] = v4.w * 0.125f;
    }
    if (tid < 128) { m_s[tid] = -INFINITY; l_s[tid] = 0.f; }

    // PV accumulators: warp owns rows wid*16..+16, thread rows g/g+8, 8 n-frags
    float acco[8][4];
    #pragma unroll
    for (int ni = 0; ni < 8; ni++)
        #pragma unroll
        for (int j = 0; j < 4; j++) acco[ni][j] = 0.f;

    const int row0 = wid * 16 + g;
    const int row1 = row0 + 8;

    for (int it = 0; it < NS / 128; it++) {
        const int t0 = it * 128;
        __syncthreads();   // previous iter's reads of Ks/Vt/Ss done

        // load K tile [t][dh] and V^T tile [dh][t]
        #pragma unroll
        for (int i = 0; i < 8; i++) {
            const int f = tid + i * 256;
            const int r = f >> 4, d4 = (f & 15) << 2;
            const float4 kv = *reinterpret_cast<const float4*>(
                &qkv[(size_t)(b * NS + t0 + r) * N3 + ND + h * NDH + d4]);
            float* kd = &Ks[r * QK_S + d4];
            kd[0] = kv.x; kd[1] = kv.y; kd[2] = kv.z; kd[3] = kv.w;
            const float4 vv = *reinterpret_cast<const float4*>(
                &qkv[(size_t)(b * NS + t0 + r) * N3 + 2 * ND + h * NDH + d4]);
            Vt[(d4 + 0) * VT_S + r] = vv.x;
            Vt[(d4 + 1) * VT_S + r] = vv.y;
            Vt[(d4 + 2) * VT_S + r] = vv.z;
            Vt[(d4 + 3) * VT_S + r] = vv.w;
        }
        __syncthreads();

        // ---- S = Q K^T : M=128, N=128, K=64; warp tile 64x32 ----
        {
            const int wm = (wid & 1) * 64;
            const int wn = (wid >> 1) * 32;
            float accs[4][4][4];
            #pragma unroll
            for (int mi = 0; mi < 4; mi++)
                #pragma unroll
                for (int ni = 0; ni < 4; ni++)
                    #pragma unroll
                    for (int j = 0; j < 4; j++) accs[mi][ni][j] = 0.f;

            #pragma unroll
            for (int ks = 0; ks < 8; ks++) {
                const int k8 = ks * 8;
                uint32_t af[4][4], bf[4][2];
                #pragma unroll
                for (int mi = 0; mi < 4; mi++) {
                    const int r0 = wm + mi * 16 + g;
                    af[mi][0] = f2tf32(Qs[r0 * QK_S + k8 + tq]);
                    af[mi][1] = f2tf32(Qs[(r0 + 8) * QK_S + k8 + tq]);
                    af[mi][2] = f2tf32(Qs[r0 * QK_S + k8 + tq + 4]);
                    af[mi][3] = f2tf32(Qs[(r0 + 8) * QK_S + k8 + tq + 4]);
                }
                #pragma unroll
                for (int ni = 0; ni < 4; ni++) {
                    const int n0 = wn + ni * 8 + g;
                    bf[ni][0] = f2tf32(Ks[n0 * QK_S + k8 + tq]);
                    bf[ni][1] = f2tf32(Ks[n0 * QK_S + k8 + tq + 4]);
                }
                #pragma unroll
                for (int mi = 0; mi < 4; mi++)
                    #pragma unroll
                    for (int ni = 0; ni < 4; ni++)
                        mma_tf32(accs[mi][ni], af[mi], bf[ni]);
            }
            // write S to smem
            #pragma unroll
            for (int mi = 0; mi < 4; mi++) {
                const int r = wm + mi * 16 + g;
                #pragma unroll
                for (int ni = 0; ni < 4; ni++) {
                    const int c = wn + ni * 8 + 2 * tq;
                    float2 s0v = {accs[mi][ni][0], accs[mi][ni][1]};
                    float2 s1v = {accs[mi][ni][2], accs[mi][ni][3]};
                    *reinterpret_cast<float2*>(&Ss[r * SS_S + c]) = s0v;
                    *reinterpret_cast<float2*>(&Ss[(r + 8) * SS_S + c]) = s1v;
                }
            }
        }
        __syncthreads();

        // ---- online softmax: 2 threads per row, 64 cols each ----
        {
            const int r = tid >> 1, h2 = tid & 1;
            const unsigned char* mrow =
                mask + ((size_t)b * NS + s0 + r) * NS + t0 + h2 * 64;
            float4* prow = reinterpret_cast<float4*>(&Ss[r * SS_S + h2 * 64]);

            float mv = -INFINITY;
            #pragma unroll
            for (int j = 0; j < 16; j++) {
                float4 s4 = prow[j];
                const uchar4 mk = reinterpret_cast<const uchar4*>(mrow)[j];
                s4.x = mk.x ? -1e18f : s4.x;
                s4.y = mk.y ? -1e18f : s4.y;
                s4.z = mk.z ? -1e18f : s4.z;
                s4.w = mk.w ? -1e18f : s4.w;
                mv = fmaxf(mv, fmaxf(fmaxf(s4.x, s4.y), fmaxf(s4.z, s4.w)));
            }
            mv = fmaxf(mv, __shfl_xor_sync(0xffffffffu, mv, 1));
            const float mo = m_s[r];
            const float nm = fmaxf(mo, mv);
            const float fc = __expf(mo - nm);

            float sum = 0.f;
            #pragma unroll
            for (int j = 0; j < 16; j++) {
                float4 s4 = prow[j];
                const uchar4 mk = reinterpret_cast<const uchar4*>(mrow)[j];
                s4.x = __expf((mk.x ? -1e18f : s4.x) - nm);
                s4.y = __expf((mk.y ? -1e18f : s4.y) - nm);
                s4.z = __expf((mk.z ? -1e18f : s4.z) - nm);
                s4.w = __expf((mk.w ? -1e18f : s4.w) - nm);
                prow[j] = s4;
                sum += s4.x + s4.y + s4.z + s4.w;
            }
            sum += __shfl_xor_sync(0xffffffffu, sum, 1);
            if (h2 == 0) {
                l_s[r] = l_s[r] * fc + sum;
                f_s[r] = fc;
                m_s[r] = nm;
            }
        }
        __syncthreads();

        // ---- rescale O, then O += P V : M=128, N=64, K=128; warp tile 16x64 ----
        {
            const float f0 = f_s[row0];
            const float f1 = f_s[row1];
            #pragma unroll
            for (int ni = 0; ni < 8; ni++) {
                acco[ni][0] *= f0; acco[ni][1] *= f0;
                acco[ni][2] *= f1; acco[ni][3] *= f1;
            }
            #pragma unroll
            for (int ks = 0; ks < 16; ks++) {
                const int k8 = ks * 8;
                uint32_t a[4];
                a[0] = f2tf32(Ss[row0 * SS_S + k8 + tq]);
                a[1] = f2tf32(Ss[row1 * SS_S + k8 + tq]);
                a[2] = f2tf32(Ss[row0 * SS_S + k8 + tq + 4]);
                a[3] = f2tf32(Ss[row1 * SS_S + k8 + tq + 4]);
                #pragma unroll
                for (int ni = 0; ni < 8; ni++) {
                    const int n0 = ni * 8 + g;
                    uint32_t bf[2];
                    bf[0] = f2tf32(Vt[n0 * VT_S + k8 + tq]);
                    bf[1] = f2tf32(Vt[n0 * VT_S + k8 + tq + 4]);
                    mma_tf32(acco[ni], a, bf);
                }
            }
        }
    }

    // ---- finalize: divide by l, write ctx[b, s, h*64+d] ----
    const float inv0 = 1.0f / l_s[row0];
    const float inv1 = 1.0f / l_s[row1];
    #pragma unroll
    for (int ni = 0; ni < 8; ni++) {
        const int col = h * NDH + ni * 8 + 2 * tq;
        float2 o0 = {acco[ni][0] * inv0, acco[ni][1] * inv0};
        float2 o1 = {acco[ni][2] * inv1, acco[ni][3] * inv1};
        *reinterpret_cast<float2*>(
            &ctx[(size_t)(b * NS + s0 + row0) * ND + col]) = o0;
        *reinterpret_cast<float2*>(
            &ctx[(size_t)(b * NS + s0 + row1) * ND + col]) = o1;
    }
}

// ---------------- host launch ----------------
extern "C" void kernel_launch(void* const* d_in, const int* in_sizes, int n_in,
                              void* d_out, int out_size) {
    const float* x   = (const float*)d_in[0];
    const unsigned char* mask = (const unsigned char*)d_in[1];
    const float* Wq  = (const float*)d_in[2];
    const float* bq  = (const float*)d_in[3];
    const float* Wk  = (const float*)d_in[4];
    const float* bk  = (const float*)d_in[5];
    const float* Wv  = (const float*)d_in[6];
    const float* bv  = (const float*)d_in[7];
    const float* Wo  = (const float*)d_in[8];
    const float* bo  = (const float*)d_in[9];
    const float* ln1g = (const float*)d_in[10];
    const float* ln1b = (const float*)d_in[11];
    const float* ln2g = (const float*)d_in[12];
    const float* ln2b = (const float*)d_in[13];
    const float* W1  = (const float*)d_in[14];
    const float* b1  = (const float*)d_in[15];
    const float* W2  = (const float*)d_in[16];
    const float* b2  = (const float*)d_in[17];
    float* out = (float*)d_out;

    float *h, *ctx, *ffn, *qkv, *wqkv, *wo, *w1, *w2, *bqkv;
    cudaGetSymbolAddress((void**)&h,    g_h);
    cudaGetSymbolAddress((void**)&ctx,  g_ctx);
    cudaGetSymbolAddress((void**)&ffn,  g_ffn);
    cudaGetSymbolAddress((void**)&qkv,  g_qkv);
    cudaGetSymbolAddress((void**)&wqkv, g_wqkv);
    cudaGetSymbolAddress((void**)&wo,   g_wo);
    cudaGetSymbolAddress((void**)&w1,   g_w1);
    cudaGetSymbolAddress((void**)&w2,   g_w2);
    cudaGetSymbolAddress((void**)&bqkv, g_bqkv);

    cudaFuncSetAttribute(mma_gemm, cudaFuncAttributeMaxDynamicSharedMemorySize,
                         GEMM_SMEM);
    cudaFuncSetAttribute(flash_kernel, cudaFuncAttributeMaxDynamicSharedMemorySize,
                         FL_SMEM);

    const dim3 tb(32, 8);

    // 0. weight transposes to [N, K] K-major (grid = (cols/32, rows/32))
    transpose_kernel<<<dim3(ND/32, ND/32), tb>>>(Wq, wqkv,              ND, ND);
    transpose_kernel<<<dim3(ND/32, ND/32), tb>>>(Wk, wqkv + (size_t)ND*ND,   ND, ND);
    transpose_kernel<<<dim3(ND/32, ND/32), tb>>>(Wv, wqkv + (size_t)2*ND*ND, ND, ND);
    transpose_kernel<<<dim3(ND/32, ND/32), tb>>>(Wo, wo, ND, ND);
    transpose_kernel<<<dim3(NF/32, ND/32), tb>>>(W1, w1, ND, NF);
    transpose_kernel<<<dim3(ND/32, NF/32), tb>>>(W2, w2, NF, ND);
    concat_bias_kernel<<<N3/256, 256>>>(bq, bk, bv, bqkv);

    // 1. LN1
    ln_kernel<<<NM, 256>>>(x, ln1g, ln1b, h);
    // 2. fused QKV projection (scale applied in flash)
    mma_gemm<<<dim3(N3/128, NM/128), 256, GEMM_SMEM>>>(N3, ND, h, wqkv, bqkv,
                                                       nullptr, qkv, 1.0f, 0);
    // 3. flash attention -> ctx
    flash_kernel<<<dim3(NS/128, NB*NH), 256, FL_SMEM>>>(qkv, mask, ctx);
    // 4. x1 = x + ctx @ Wo + bo -> out
    mma_gemm<<<dim3(ND/128, NM/128), 256, GEMM_SMEM>>>(ND, ND, ctx, wo, bo, x, out, 1.0f, 0);
    // 5. LN2
    ln_kernel<<<NM, 256>>>(out, ln2g, ln2b, h);
    // 6. ffn = relu(h @ W1 + b1)
    mma_gemm<<<dim3(NF/128, NM/128), 256, GEMM_SMEM>>>(NF, ND, h, w1, b1, nullptr, ffn, 1.0f, 1);
    // 7. out = x1 + ffn @ W2 + b2
    mma_gemm<<<dim3(ND/128, NM/128), 256, GEMM_SMEM>>>(ND, NF, ffn, w2, b2, out, out, 1.0f, 0);
}

// round 7
// speedup vs baseline: 2.4995x; 1.3693x over previous
#include <cuda_runtime.h>
#include <math.h>
#include <stdint.h>

// Problem constants
#define NB 2
#define NS 2048
#define ND 1024
#define NH 16
#define NDH 64
#define NF 4096
#define NM (NB*NS)          // 4096 rows total
#define N3 (3*ND)           // 3072

// ---------------- scratch (device globals: allocation-free rule) ----------------
__device__ float g_h   [(size_t)NM*ND];
__device__ float g_ctx [(size_t)NM*ND];
__device__ float g_ffn [(size_t)NM*NF];
__device__ float g_qkv [(size_t)NM*N3];
__device__ float g_wqkv[(size_t)3*ND*ND];   // [3072,1024] K-major concat
__device__ float g_wo  [(size_t)ND*ND];
__device__ float g_w1  [(size_t)NF*ND];     // W1^T: [F, D]
__device__ float g_w2  [(size_t)ND*NF];     // W2^T: [D, F]
__device__ float g_bqkv[N3];

// ======================= helpers =======================
__device__ __forceinline__ uint32_t smem_u32(const void* p) {
    uint32_t a;
    asm("{ .reg .u64 t; cvta.to.shared.u64 t, %1; cvt.u32.u64 %0, t; }"
        : "=r"(a) : "l"(p));
    return a;
}

__device__ __forceinline__ uint32_t f2tf32(float f) {
    uint32_t u;
    asm("cvt.rna.tf32.f32 %0, %1;" : "=r"(u) : "f"(f));
    return u;
}
__device__ __forceinline__ float f2tf32f(float f) {
    return __uint_as_float(f2tf32(f));
}

__device__ __forceinline__ void mma_tf32(float* d, const uint32_t* a, const uint32_t* b) {
    asm volatile(
        "mma.sync.aligned.m16n8k8.row.col.f32.tf32.tf32.f32 "
        "{%0,%1,%2,%3}, {%4,%5,%6,%7}, {%8,%9}, {%0,%1,%2,%3};"
        : "+f"(d[0]), "+f"(d[1]), "+f"(d[2]), "+f"(d[3])
        : "r"(a[0]), "r"(a[1]), "r"(a[2]), "r"(a[3]), "r"(b[0]), "r"(b[1]));
}

// ---------------- transpose helper (device) ----------------
__device__ __forceinline__ void do_transpose(const float* __restrict__ in,
                                             float* __restrict__ out,
                                             int rows, int cols,
                                             int bx, int by,
                                             float (*tile)[33]) {
    const int c0 = bx * 32, r0 = by * 32;
    const int tx = threadIdx.x & 31, ty = threadIdx.x >> 5;   // 32x8
    #pragma unroll
    for (int j = 0; j < 32; j += 8)
        tile[ty + j][tx] = in[(size_t)(r0 + ty + j) * cols + c0 + tx];
    __syncthreads();
    #pragma unroll
    for (int j = 0; j < 32; j += 8)
        out[(size_t)(c0 + ty + j) * rows + r0 + tx] = tile[tx][ty + j];
}

// prepA: Wq, Wk, Wv -> wqkv.  grid (32, 32, 3), 256 threads
__global__ void prepA_kernel(const float* __restrict__ Wq, const float* __restrict__ Wk,
                             const float* __restrict__ Wv, float* __restrict__ wqkv) {
    __shared__ float tile[32][33];
    const float* src = (blockIdx.z == 0) ? Wq : (blockIdx.z == 1 ? Wk : Wv);
    float* dst = wqkv + (size_t)blockIdx.z * ND * ND;
    do_transpose(src, dst, ND, ND, blockIdx.x, blockIdx.y, tile);
}

// prepB: Wo (z=0, bx<32) and W1 (z=1). grid (128, 32, 2)
__global__ void prepB_kernel(const float* __restrict__ Wo, float* __restrict__ wo,
                             const float* __restrict__ W1, float* __restrict__ w1) {
    __shared__ float tile[32][33];
    if (blockIdx.z == 0) {
        if (blockIdx.x >= 32) return;
        do_transpose(Wo, wo, ND, ND, blockIdx.x, blockIdx.y, tile);
    } else {
        do_transpose(W1, w1, ND, NF, blockIdx.x, blockIdx.y, tile);
    }
}

// prepC: W2 (z=0) and bias concat (z=1, first 12 blocks of row 0). grid (32, 128, 2)
__global__ void prepC_kernel(const float* __restrict__ W2, float* __restrict__ w2,
                             const float* __restrict__ bq, const float* __restrict__ bk,
                             const float* __restrict__ bv, float* __restrict__ bqkv) {
    __shared__ float tile[32][33];
    if (blockIdx.z == 0) {
        do_transpose(W2, w2, NF, ND, blockIdx.x, blockIdx.y, tile);
    } else {
        if (blockIdx.y != 0 || blockIdx.x >= 12) return;
        const int i = blockIdx.x * 256 + threadIdx.x;
        bqkv[i] = (i < ND) ? bq[i] : (i < 2 * ND ? bk[i - ND] : bv[i - 2 * ND]);
    }
}

// ---------------- LayerNorm ----------------
__global__ void ln_kernel(const float* __restrict__ x,
                          const float* __restrict__ g,
                          const float* __restrict__ b,
                          float* __restrict__ out) {
    __shared__ float red[8];
    const int row = blockIdx.x;
    const int t = threadIdx.x;
    const float4 v = reinterpret_cast<const float4*>(x + (size_t)row * ND)[t];

    float s = v.x + v.y + v.z + v.w;
    #pragma unroll
    for (int o = 16; o; o >>= 1) s += __shfl_xor_sync(0xffffffffu, s, o);
    if ((t & 31) == 0) red[t >> 5] = s;
    __syncthreads();
    float tot = 0.f;
    #pragma unroll
    for (int i = 0; i < 8; i++) tot += red[i];
    const float mean = tot * (1.0f / ND);
    __syncthreads();

    const float dx = v.x - mean, dy = v.y - mean, dz = v.z - mean, dw = v.w - mean;
    float ss = dx*dx + dy*dy + dz*dz + dw*dw;
    #pragma unroll
    for (int o = 16; o; o >>= 1) ss += __shfl_xor_sync(0xffffffffu, ss, o);
    if ((t & 31) == 0) red[t >> 5] = ss;
    __syncthreads();
    float var = 0.f;
    #pragma unroll
    for (int i = 0; i < 8; i++) var += red[i];
    var *= (1.0f / ND);
    const float inv = rsqrtf(var + 1e-5f);

    const float4 gg = reinterpret_cast<const float4*>(g)[t];
    const float4 bb = reinterpret_cast<const float4*>(b)[t];
    float4 o4;
    o4.x = dx * inv * gg.x + bb.x;
    o4.y = dy * inv * gg.y + bb.y;
    o4.z = dz * inv * gg.z + bb.z;
    o4.w = dw * inv * gg.w + bb.w;
    reinterpret_cast<float4*>(out + (size_t)row * ND)[t] = o4;
}

// ================ tf32 mma.sync GEMM: C = epi(A[M,K] @ Wt[N,K]^T) ================
// BM=128, BN=128, BK=32. Tiles pre-converted to tf32 at SMEM store (LDG->cvt->STS,
// double buffered). Fragment loads are raw uint32 (no per-load cvt).
#define SROW 36
#define TILE_F (128 * SROW)
#define GEMM_SMEM (4 * TILE_F * 4)

__global__ __launch_bounds__(256)
void mma_gemm(int N, int K,
              const float* __restrict__ A, const float* __restrict__ Wt,
              const float* __restrict__ bias, const float* __restrict__ res,
              float* __restrict__ C, float scale, int relu) {
    extern __shared__ float sm[];
    float* sAf = sm;
    float* sBf = sm + 2 * TILE_F;

    const int tid = threadIdx.x;
    const int wid = tid >> 5, lane = tid & 31;
    const int g = lane >> 2, t = lane & 3;
    const int wm = (wid & 1) * 64;
    const int wn = (wid >> 1) * 32;
    const int bm = blockIdx.y * 128;
    const int bn = blockIdx.x * 128;

    const int lr = tid >> 3;             // 0..31
    const int lc = (tid & 7) << 2;       // 0..28

    float acc[4][4][4];
    #pragma unroll
    for (int mi = 0; mi < 4; mi++)
        #pragma unroll
        for (int ni = 0; ni < 4; ni++)
            #pragma unroll
            for (int j = 0; j < 4; j++) acc[mi][ni][j] = 0.f;

    const int numT = K >> 5;

    float4 pa[4], pb[4];
    auto gload = [&](int tt) {
        const int k0 = tt * 32;
        #pragma unroll
        for (int i = 0; i < 4; i++) {
            pa[i] = *reinterpret_cast<const float4*>(&A[(size_t)(bm + lr + i * 32) * K + k0 + lc]);
            pb[i] = *reinterpret_cast<const float4*>(&Wt[(size_t)(bn + lr + i * 32) * K + k0 + lc]);
        }
    };
    auto sstore = [&](int buf) {
        float* As = sAf + buf * TILE_F;
        float* Bs = sBf + buf * TILE_F;
        #pragma unroll
        for (int i = 0; i < 4; i++) {
            const int r = lr + i * 32;
            uint4 ua = { f2tf32(pa[i].x), f2tf32(pa[i].y), f2tf32(pa[i].z), f2tf32(pa[i].w) };
            uint4 ub = { f2tf32(pb[i].x), f2tf32(pb[i].y), f2tf32(pb[i].z), f2tf32(pb[i].w) };
            *reinterpret_cast<uint4*>(&As[r * SROW + lc]) = ua;
            *reinterpret_cast<uint4*>(&Bs[r * SROW + lc]) = ub;
        }
    };

    gload(0);
    sstore(0);

    for (int tt = 0; tt < numT; tt++) {
        const int buf = tt & 1;
        __syncthreads();                       // publish buf's stores
        if (tt + 1 < numT) gload(tt + 1);      // prefetch next (LDG overlaps compute)

        const uint32_t* As = reinterpret_cast<const uint32_t*>(sAf + buf * TILE_F);
        const uint32_t* Bs = reinterpret_cast<const uint32_t*>(sBf + buf * TILE_F);

        #pragma unroll
        for (int ks = 0; ks < 4; ks++) {
            const int k8 = ks * 8;
            uint32_t af[4][4], bf[4][2];
            #pragma unroll
            for (int mi = 0; mi < 4; mi++) {
                const int r0 = wm + mi * 16 + g;
                af[mi][0] = As[r0 * SROW + k8 + t];
                af[mi][1] = As[(r0 + 8) * SROW + k8 + t];
                af[mi][2] = As[r0 * SROW + k8 + t + 4];
                af[mi][3] = As[(r0 + 8) * SROW + k8 + t + 4];
            }
            #pragma unroll
            for (int ni = 0; ni < 4; ni++) {
                const int n0 = wn + ni * 8 + g;
                bf[ni][0] = Bs[n0 * SROW + k8 + t];
                bf[ni][1] = Bs[n0 * SROW + k8 + t + 4];
            }
            #pragma unroll
            for (int mi = 0; mi < 4; mi++)
                #pragma unroll
                for (int ni = 0; ni < 4; ni++)
                    mma_tf32(acc[mi][ni], af[mi], bf[ni]);
        }
        if (tt + 1 < numT) sstore((tt + 1) & 1);   // buf^1 readers finished before top sync
    }

    #pragma unroll
    for (int mi = 0; mi < 4; mi++) {
        const int row0 = bm + wm + mi * 16 + g;
        #pragma unroll
        for (int ni = 0; ni < 4; ni++) {
            const int col = bn + wn + ni * 8 + 2 * t;
            const float2 b2 = *reinterpret_cast<const float2*>(&bias[col]);
            float v0 = acc[mi][ni][0] + b2.x;
            float v1 = acc[mi][ni][1] + b2.y;
            float v2 = acc[mi][ni][2] + b2.x;
            float v3 = acc[mi][ni][3] + b2.y;
            if (relu) {
                v0 = fmaxf(v0, 0.f); v1 = fmaxf(v1, 0.f);
                v2 = fmaxf(v2, 0.f); v3 = fmaxf(v3, 0.f);
            }
            v0 *= scale; v1 *= scale; v2 *= scale; v3 *= scale;
            if (res) {
                const float2 r0 = *reinterpret_cast<const float2*>(
                    &res[(size_t)row0 * N + col]);
                const float2 r1 = *reinterpret_cast<const float2*>(
                    &res[(size_t)(row0 + 8) * N + col]);
                v0 += r0.x; v1 += r0.y; v2 += r1.x; v3 += r1.y;
            }
            float2 o0 = {v0, v1}, o1 = {v2, v3};
            *reinterpret_cast<float2*>(&C[(size_t)row0 * N + col]) = o0;
            *reinterpret_cast<float2*>(&C[(size_t)(row0 + 8) * N + col]) = o1;
        }
    }
}

// ================ Flash attention ================
// grid (NS/128, NB*NH), 256 threads. Q tile 128x64, 16 K/V tiles of 128.
// Q/K/V/P stored in SMEM pre-rounded to tf32; fragment loads are raw uint32.
#define QK_S 68
#define SS_S 132
#define VT_S 133
#define FL_SMEM ((128*QK_S + 128*QK_S + 64*VT_S + 128*SS_S + 3*128) * 4)

__global__ __launch_bounds__(256)
void flash_kernel(const float* __restrict__ qkv,
                  const unsigned char* __restrict__ mask,
                  float* __restrict__ ctx) {
    extern __shared__ float fs[];
    float* Qs  = fs;                        // [128][68] tf32 bits
    float* Ks  = Qs + 128 * QK_S;           // [128][68] tf32 bits
    float* Vt  = Ks + 128 * QK_S;           // [64][133] tf32 bits (V transposed)
    float* Ss  = Vt + 64 * VT_S;            // [128][132] S (fp32) then P (tf32 bits)
    float* m_s = Ss + 128 * SS_S;
    float* l_s = m_s + 128;
    float* f_s = l_s + 128;

    const int tid = threadIdx.x;
    const int wid = tid >> 5, lane = tid & 31;
    const int g = lane >> 2, tq = lane & 3;
    const int bh = blockIdx.y;
    const int b = bh >> 4, h = bh & 15;
    const int s0 = blockIdx.x * 128;

    // load Q tile (scale + round to tf32 once)
    #pragma unroll
    for (int i = 0; i < 8; i++) {
        const int f = tid + i * 256;
        const int r = f >> 4, d4 = (f & 15) << 2;
        const float4 v4 = *reinterpret_cast<const float4*>(
            &qkv[(size_t)(b * NS + s0 + r) * N3 + h * NDH + d4]);
        float* dst = &Qs[r * QK_S + d4];
        dst[0] = f2tf32f(v4.x * 0.125f);
        dst[1] = f2tf32f(v4.y * 0.125f);
        dst[2] = f2tf32f(v4.z * 0.125f);
        dst[3] = f2tf32f(v4.w * 0.125f);
    }
    if (tid < 128) { m_s[tid] = -INFINITY; l_s[tid] = 0.f; }

    float acco[8][4];
    #pragma unroll
    for (int ni = 0; ni < 8; ni++)
        #pragma unroll
        for (int j = 0; j < 4; j++) acco[ni][j] = 0.f;

    const int row0 = wid * 16 + g;
    const int row1 = row0 + 8;

    for (int it = 0; it < NS / 128; it++) {
        const int t0 = it * 128;
        __syncthreads();

        // load K and V^T tiles, rounded to tf32 at store
        #pragma unroll
        for (int i = 0; i < 8; i++) {
            const int f = tid + i * 256;
            const int r = f >> 4, d4 = (f & 15) << 2;
            const float4 kv = *reinterpret_cast<const float4*>(
                &qkv[(size_t)(b * NS + t0 + r) * N3 + ND + h * NDH + d4]);
            float* kd = &Ks[r * QK_S + d4];
            kd[0] = f2tf32f(kv.x); kd[1] = f2tf32f(kv.y);
            kd[2] = f2tf32f(kv.z); kd[3] = f2tf32f(kv.w);
            const float4 vv = *reinterpret_cast<const float4*>(
                &qkv[(size_t)(b * NS + t0 + r) * N3 + 2 * ND + h * NDH + d4]);
            Vt[(d4 + 0) * VT_S + r] = f2tf32f(vv.x);
            Vt[(d4 + 1) * VT_S + r] = f2tf32f(vv.y);
            Vt[(d4 + 2) * VT_S + r] = f2tf32f(vv.z);
            Vt[(d4 + 3) * VT_S + r] = f2tf32f(vv.w);
        }
        __syncthreads();

        // ---- S = Q K^T : M=128, N=128, K=64; warp tile 64x32 ----
        {
            const uint32_t* Qu = reinterpret_cast<const uint32_t*>(Qs);
            const uint32_t* Ku = reinterpret_cast<const uint32_t*>(Ks);
            const int wm = (wid & 1) * 64;
            const int wn = (wid >> 1) * 32;
            float accs[4][4][4];
            #pragma unroll
            for (int mi = 0; mi < 4; mi++)
                #pragma unroll
                for (int ni = 0; ni < 4; ni++)
                    #pragma unroll
                    for (int j = 0; j < 4; j++) accs[mi][ni][j] = 0.f;

            #pragma unroll
            for (int ks = 0; ks < 8; ks++) {
                const int k8 = ks * 8;
                uint32_t af[4][4], bf[4][2];
                #pragma unroll
                for (int mi = 0; mi < 4; mi++) {
                    const int r0 = wm + mi * 16 + g;
                    af[mi][0] = Qu[r0 * QK_S + k8 + tq];
                    af[mi][1] = Qu[(r0 + 8) * QK_S + k8 + tq];
                    af[mi][2] = Qu[r0 * QK_S + k8 + tq + 4];
                    af[mi][3] = Qu[(r0 + 8) * QK_S + k8 + tq + 4];
                }
                #pragma unroll
                for (int ni = 0; ni < 4; ni++) {
                    const int n0 = wn + ni * 8 + g;
                    bf[ni][0] = Ku[n0 * QK_S + k8 + tq];
                    bf[ni][1] = Ku[n0 * QK_S + k8 + tq + 4];
                }
                #pragma unroll
                for (int mi = 0; mi < 4; mi++)
                    #pragma unroll
                    for (int ni = 0; ni < 4; ni++)
                        mma_tf32(accs[mi][ni], af[mi], bf[ni]);
            }
            #pragma unroll
            for (int mi = 0; mi < 4; mi++) {
                const int r = wm + mi * 16 + g;
                #pragma unroll
                for (int ni = 0; ni < 4; ni++) {
                    const int c = wn + ni * 8 + 2 * tq;
                    float2 s0v = {accs[mi][ni][0], accs[mi][ni][1]};
                    float2 s1v = {accs[mi][ni][2], accs[mi][ni][3]};
                    *reinterpret_cast<float2*>(&Ss[r * SS_S + c]) = s0v;
                    *reinterpret_cast<float2*>(&Ss[(r + 8) * SS_S + c]) = s1v;
                }
            }
        }
        __syncthreads();

        // ---- online softmax: 2 threads per row; write P as tf32 bits ----
        {
            const int r = tid >> 1, h2 = tid & 1;
            const unsigned char* mrow =
                mask + ((size_t)b * NS + s0 + r) * NS + t0 + h2 * 64;
            float4* prow = reinterpret_cast<float4*>(&Ss[r * SS_S + h2 * 64]);

            float mv = -INFINITY;
            #pragma unroll
            for (int j = 0; j < 16; j++) {
                float4 s4 = prow[j];
                const uchar4 mk = reinterpret_cast<const uchar4*>(mrow)[j];
                s4.x = mk.x ? -1e18f : s4.x;
                s4.y = mk.y ? -1e18f : s4.y;
                s4.z = mk.z ? -1e18f : s4.z;
                s4.w = mk.w ? -1e18f : s4.w;
                mv = fmaxf(mv, fmaxf(fmaxf(s4.x, s4.y), fmaxf(s4.z, s4.w)));
            }
            mv = fmaxf(mv, __shfl_xor_sync(0xffffffffu, mv, 1));
            const float mo = m_s[r];
            const float nm = fmaxf(mo, mv);
            const float fc = __expf(mo - nm);

            float sum = 0.f;
            #pragma unroll
            for (int j = 0; j < 16; j++) {
                float4 s4 = prow[j];
                const uchar4 mk = reinterpret_cast<const uchar4*>(mrow)[j];
                s4.x = __expf((mk.x ? -1e18f : s4.x) - nm);
                s4.y = __expf((mk.y ? -1e18f : s4.y) - nm);
                s4.z = __expf((mk.z ? -1e18f : s4.z) - nm);
                s4.w = __expf((mk.w ? -1e18f : s4.w) - nm);
                sum += s4.x + s4.y + s4.z + s4.w;
                s4.x = f2tf32f(s4.x); s4.y = f2tf32f(s4.y);
                s4.z = f2tf32f(s4.z); s4.w = f2tf32f(s4.w);
                prow[j] = s4;
            }
            sum += __shfl_xor_sync(0xffffffffu, sum, 1);
            if (h2 == 0) {
                l_s[r] = l_s[r] * fc + sum;
                f_s[r] = fc;
                m_s[r] = nm;
            }
        }
        __syncthreads();

        // ---- O = O*fc + P V : M=128, N=64, K=128; warp tile 16x64 ----
        {
            const uint32_t* Su = reinterpret_cast<const uint32_t*>(Ss);
            const uint32_t* Vu = reinterpret_cast<const uint32_t*>(Vt);
            const float f0 = f_s[row0];
            const float f1 = f_s[row1];
            #pragma unroll
            for (int ni = 0; ni < 8; ni++) {
                acco[ni][0] *= f0; acco[ni][1] *= f0;
                acco[ni][2] *= f1; acco[ni][3] *= f1;
            }
            #pragma unroll
            for (int ks = 0; ks < 16; ks++) {
                const int k8 = ks * 8;
                uint32_t a[4];
                a[0] = Su[row0 * SS_S + k8 + tq];
                a[1] = Su[row1 * SS_S + k8 + tq];
                a[2] = Su[row0 * SS_S + k8 + tq + 4];
                a[3] = Su[row1 * SS_S + k8 + tq + 4];
                #pragma unroll
                for (int ni = 0; ni < 8; ni++) {
                    const int n0 = ni * 8 + g;
                    uint32_t bf[2];
                    bf[0] = Vu[n0 * VT_S + k8 + tq];
                    bf[1] = Vu[n0 * VT_S + k8 + tq + 4];
                    mma_tf32(acco[ni], a, bf);
                }
            }
        }
    }

    const float inv0 = 1.0f / l_s[row0];
    const float inv1 = 1.0f / l_s[row1];
    #pragma unroll
    for (int ni = 0; ni < 8; ni++) {
        const int col = h * NDH + ni * 8 + 2 * tq;
        float2 o0 = {acco[ni][0] * inv0, acco[ni][1] * inv0};
        float2 o1 = {acco[ni][2] * inv1, acco[ni][3] * inv1};
        *reinterpret_cast<float2*>(
            &ctx[(size_t)(b * NS + s0 + row0) * ND + col]) = o0;
        *reinterpret_cast<float2*>(
            &ctx[(size_t)(b * NS + s0 + row1) * ND + col]) = o1;
    }
}

// ---------------- host launch ----------------
extern "C" void kernel_launch(void* const* d_in, const int* in_sizes, int n_in,
                              void* d_out, int out_size) {
    const float* x   = (const float*)d_in[0];
    const unsigned char* mask = (const unsigned char*)d_in[1];
    const float* Wq  = (const float*)d_in[2];
    const float* bq  = (const float*)d_in[3];
    const float* Wk  = (const float*)d_in[4];
    const float* bk  = (const float*)d_in[5];
    const float* Wv  = (const float*)d_in[6];
    const float* bv  = (const float*)d_in[7];
    const float* Wo  = (const float*)d_in[8];
    const float* bo  = (const float*)d_in[9];
    const float* ln1g = (const float*)d_in[10];
    const float* ln1b = (const float*)d_in[11];
    const float* ln2g = (const float*)d_in[12];
    const float* ln2b = (const float*)d_in[13];
    const float* W1  = (const float*)d_in[14];
    const float* b1  = (const float*)d_in[15];
    const float* W2  = (const float*)d_in[16];
    const float* b2  = (const float*)d_in[17];
    float* out = (float*)d_out;

    float *h, *ctx, *ffn, *qkv, *wqkv, *wo, *w1, *w2, *bqkv;
    cudaGetSymbolAddress((void**)&h,    g_h);
    cudaGetSymbolAddress((void**)&ctx,  g_ctx);
    cudaGetSymbolAddress((void**)&ffn,  g_ffn);
    cudaGetSymbolAddress((void**)&qkv,  g_qkv);
    cudaGetSymbolAddress((void**)&wqkv, g_wqkv);
    cudaGetSymbolAddress((void**)&wo,   g_wo);
    cudaGetSymbolAddress((void**)&w1,   g_w1);
    cudaGetSymbolAddress((void**)&w2,   g_w2);
    cudaGetSymbolAddress((void**)&bqkv, g_bqkv);

    cudaFuncSetAttribute(mma_gemm, cudaFuncAttributeMaxDynamicSharedMemorySize,
                         GEMM_SMEM);
    cudaFuncSetAttribute(flash_kernel, cudaFuncAttributeMaxDynamicSharedMemorySize,
                         FL_SMEM);

    // launch order arranged so ncu (-s 5) profiles flash_kernel:
    // 0:ln1  1:prepA  2:prepB  3:prepC  4:qkv_gemm  5:flash  ...
    ln_kernel<<<NM, 256>>>(x, ln1g, ln1b, h);
    prepA_kernel<<<dim3(32, 32, 3), 256>>>(Wq, Wk, Wv, wqkv);
    prepB_kernel<<<dim3(128, 32, 2), 256>>>(Wo, wo, W1, w1);
    prepC_kernel<<<dim3(32, 128, 2), 256>>>(W2, w2, bq, bk, bv, bqkv);

    // fused QKV projection (scale applied in flash)
    mma_gemm<<<dim3(N3/128, NM/128), 256, GEMM_SMEM>>>(N3, ND, h, wqkv, bqkv,
                                                       nullptr, qkv, 1.0f, 0);
    // flash attention -> ctx
    flash_kernel<<<dim3(NS/128, NB*NH), 256, FL_SMEM>>>(qkv, mask, ctx);
    // x1 = x + ctx @ Wo + bo -> out
    mma_gemm<<<dim3(ND/128, NM/128), 256, GEMM_SMEM>>>(ND, ND, ctx, wo, bo, x, out, 1.0f, 0);
    // LN2
    ln_kernel<<<NM, 256>>>(out, ln2g, ln2b, h);
    // ffn = relu(h @ W1 + b1)
    mma_gemm<<<dim3(NF/128, NM/128), 256, GEMM_SMEM>>>(NF, ND, h, w1, b1, nullptr, ffn, 1.0f, 1);
    // out = x1 + ffn @ W2 + b2
    mma_gemm<<<dim3(ND/128, NM/128), 256, GEMM_SMEM>>>(ND, NF, ffn, w2, b2, out, out, 1.0f, 0);
}

// round 8
// speedup vs baseline: 2.8629x; 1.1454x over previous
#include <cuda_runtime.h>
#include <math.h>
#include <stdint.h>

// Problem constants
#define NB 2
#define NS 2048
#define ND 1024
#define NH 16
#define NDH 64
#define NF 4096
#define NM (NB*NS)          // 4096 rows total
#define N3 (3*ND)           // 3072

// ---------------- scratch (device globals: allocation-free rule) ----------------
__device__ float g_h   [(size_t)NM*ND];     // LN output (tf32-rounded)
__device__ float g_ctx [(size_t)NM*ND];     // flash output (tf32-rounded)
__device__ float g_ffn [(size_t)NM*NF];     // relu output (tf32-rounded)
__device__ float g_qkv [(size_t)NM*N3];     // qkv (tf32-rounded)
__device__ float g_wqkv[(size_t)3*ND*ND];   // [3072,1024] K-major, tf32-rounded
__device__ float g_wo  [(size_t)ND*ND];     // tf32-rounded
__device__ float g_w1  [(size_t)NF*ND];     // tf32-rounded
__device__ float g_w2  [(size_t)ND*NF];     // tf32-rounded
__device__ float g_bqkv[N3];

// ======================= helpers =======================
__device__ __forceinline__ uint32_t smem_u32(const void* p) {
    uint32_t a;
    asm("{ .reg .u64 t; cvta.to.shared.u64 t, %1; cvt.u32.u64 %0, t; }"
        : "=r"(a) : "l"(p));
    return a;
}

__device__ __forceinline__ uint32_t f2tf32(float f) {
    uint32_t u;
    asm("cvt.rna.tf32.f32 %0, %1;" : "=r"(u) : "f"(f));
    return u;
}
__device__ __forceinline__ float f2tf32f(float f) {
    return __uint_as_float(f2tf32(f));
}

__device__ __forceinline__ void mma_tf32(float* d, const uint32_t* a, const uint32_t* b) {
    asm volatile(
        "mma.sync.aligned.m16n8k8.row.col.f32.tf32.tf32.f32 "
        "{%0,%1,%2,%3}, {%4,%5,%6,%7}, {%8,%9}, {%0,%1,%2,%3};"
        : "+f"(d[0]), "+f"(d[1]), "+f"(d[2]), "+f"(d[3])
        : "r"(a[0]), "r"(a[1]), "r"(a[2]), "r"(a[3]), "r"(b[0]), "r"(b[1]));
}

#define CP_ASYNC16(dst, src) \
    asm volatile("cp.async.cg.shared.global [%0], [%1], 16;" :: "r"(dst), "l"(src))
#define CP_COMMIT() asm volatile("cp.async.commit_group;" ::: "memory")
#define CP_WAIT(n)  asm volatile("cp.async.wait_group %0;" :: "n"(n) : "memory")

// ---------------- transpose helper: out = tf32(in^T) ----------------
__device__ __forceinline__ void do_transpose(const float* __restrict__ in,
                                             float* __restrict__ out,
                                             int rows, int cols,
                                             int bx, int by,
                                             float (*tile)[33]) {
    const int c0 = bx * 32, r0 = by * 32;
    const int tx = threadIdx.x & 31, ty = threadIdx.x >> 5;   // 32x8
    #pragma unroll
    for (int j = 0; j < 32; j += 8)
        tile[ty + j][tx] = in[(size_t)(r0 + ty + j) * cols + c0 + tx];
    __syncthreads();
    #pragma unroll
    for (int j = 0; j < 32; j += 8)
        out[(size_t)(c0 + ty + j) * rows + r0 + tx] = f2tf32f(tile[tx][ty + j]);
}

// prepA: Wq, Wk, Wv -> wqkv. grid (32, 32, 3)
__global__ void prepA_kernel(const float* __restrict__ Wq, const float* __restrict__ Wk,
                             const float* __restrict__ Wv, float* __restrict__ wqkv) {
    __shared__ float tile[32][33];
    const float* src = (blockIdx.z == 0) ? Wq : (blockIdx.z == 1 ? Wk : Wv);
    float* dst = wqkv + (size_t)blockIdx.z * ND * ND;
    do_transpose(src, dst, ND, ND, blockIdx.x, blockIdx.y, tile);
}

// prepB: Wo (z=0, bx<32) and W1 (z=1). grid (128, 32, 2)
__global__ void prepB_kernel(const float* __restrict__ Wo, float* __restrict__ wo,
                             const float* __restrict__ W1, float* __restrict__ w1) {
    __shared__ float tile[32][33];
    if (blockIdx.z == 0) {
        if (blockIdx.x >= 32) return;
        do_transpose(Wo, wo, ND, ND, blockIdx.x, blockIdx.y, tile);
    } else {
        do_transpose(W1, w1, ND, NF, blockIdx.x, blockIdx.y, tile);
    }
}

// prepC: W2 (z=0) and bias concat (z=1). grid (32, 128, 2)
__global__ void prepC_kernel(const float* __restrict__ W2, float* __restrict__ w2,
                             const float* __restrict__ bq, const float* __restrict__ bk,
                             const float* __restrict__ bv, float* __restrict__ bqkv) {
    __shared__ float tile[32][33];
    if (blockIdx.z == 0) {
        do_transpose(W2, w2, NF, ND, blockIdx.x, blockIdx.y, tile);
    } else {
        if (blockIdx.y != 0 || blockIdx.x >= 12) return;
        const int i = blockIdx.x * 256 + threadIdx.x;
        bqkv[i] = (i < ND) ? bq[i] : (i < 2 * ND ? bk[i - ND] : bv[i - 2 * ND]);
    }
}

// ---------------- LayerNorm (output tf32-rounded; only feeds GEMM A) ----------------
__global__ void ln_kernel(const float* __restrict__ x,
                          const float* __restrict__ g,
                          const float* __restrict__ b,
                          float* __restrict__ out) {
    __shared__ float red[8];
    const int row = blockIdx.x;
    const int t = threadIdx.x;
    const float4 v = reinterpret_cast<const float4*>(x + (size_t)row * ND)[t];

    float s = v.x + v.y + v.z + v.w;
    #pragma unroll
    for (int o = 16; o; o >>= 1) s += __shfl_xor_sync(0xffffffffu, s, o);
    if ((t & 31) == 0) red[t >> 5] = s;
    __syncthreads();
    float tot = 0.f;
    #pragma unroll
    for (int i = 0; i < 8; i++) tot += red[i];
    const float mean = tot * (1.0f / ND);
    __syncthreads();

    const float dx = v.x - mean, dy = v.y - mean, dz = v.z - mean, dw = v.w - mean;
    float ss = dx*dx + dy*dy + dz*dz + dw*dw;
    #pragma unroll
    for (int o = 16; o; o >>= 1) ss += __shfl_xor_sync(0xffffffffu, ss, o);
    if ((t & 31) == 0) red[t >> 5] = ss;
    __syncthreads();
    float var = 0.f;
    #pragma unroll
    for (int i = 0; i < 8; i++) var += red[i];
    var *= (1.0f / ND);
    const float inv = rsqrtf(var + 1e-5f);

    const float4 gg = reinterpret_cast<const float4*>(g)[t];
    const float4 bb = reinterpret_cast<const float4*>(b)[t];
    float4 o4;
    o4.x = f2tf32f(dx * inv * gg.x + bb.x);
    o4.y = f2tf32f(dy * inv * gg.y + bb.y);
    o4.z = f2tf32f(dz * inv * gg.z + bb.z);
    o4.w = f2tf32f(dw * inv * gg.w + bb.w);
    reinterpret_cast<float4*>(out + (size_t)row * ND)[t] = o4;
}

// ================ tf32 mma.sync GEMM: C = epi(A[M,K] @ Wt[N,K]^T) ================
// BM=128, BN=256, BK=32. 8 warps, warp tile 64x64 (4x8 of m16n8k8).
// Inputs pre-rounded to tf32 in GMEM -> pure cp.async double buffering, zero cvt.
#define SROW 36
#define A_TILE_F (128 * SROW)
#define B_TILE_F (256 * SROW)
#define GEMM_SMEM ((2*A_TILE_F + 2*B_TILE_F) * 4)   // 110592 B

__global__ __launch_bounds__(256)
void mma_gemm(int N, int K,
              const float* __restrict__ A, const float* __restrict__ Wt,
              const float* __restrict__ bias, const float* __restrict__ res,
              float* __restrict__ C, float scale, int relu, int rnd) {
    extern __shared__ float sm[];
    float* sAf = sm;                       // [2][128][36]
    float* sBf = sm + 2 * A_TILE_F;        // [2][256][36]
    const uint32_t sA_u = smem_u32(sAf);
    const uint32_t sB_u = smem_u32(sBf);

    const int tid = threadIdx.x;
    const int wid = tid >> 5, lane = tid & 31;
    const int g = lane >> 2, t = lane & 3;
    const int wm = (wid & 1) * 64;         // 2 warps over M
    const int wn = (wid >> 1) * 64;        // 4 warps over N
    const int bm = blockIdx.y * 128;
    const int bn = blockIdx.x * 256;

    const int lr = tid >> 3;               // 0..31
    const int lc = (tid & 7) << 2;         // 0..28

    float acc[4][8][4];
    #pragma unroll
    for (int mi = 0; mi < 4; mi++)
        #pragma unroll
        for (int ni = 0; ni < 8; ni++)
            #pragma unroll
            for (int j = 0; j < 4; j++) acc[mi][ni][j] = 0.f;

    const int numT = K >> 5;

    auto load_tile = [&](int tt, int buf) {
        const int k0 = tt * 32;
        #pragma unroll
        for (int i = 0; i < 4; i++) {
            const int r = lr + i * 32;
            CP_ASYNC16(sA_u + ((uint32_t)buf * A_TILE_F + r * SROW + lc) * 4u,
                       &A[(size_t)(bm + r) * K + k0 + lc]);
        }
        #pragma unroll
        for (int i = 0; i < 8; i++) {
            const int r = lr + i * 32;
            CP_ASYNC16(sB_u + ((uint32_t)buf * B_TILE_F + r * SROW + lc) * 4u,
                       &Wt[(size_t)(bn + r) * K + k0 + lc]);
        }
    };

    load_tile(0, 0);
    CP_COMMIT();

    for (int tt = 0; tt < numT; tt++) {
        const int buf = tt & 1;
        if (tt + 1 < numT) {
            load_tile(tt + 1, buf ^ 1);
            CP_COMMIT();
            CP_WAIT(1);
        } else {
            CP_WAIT(0);
        }
        __syncthreads();

        const uint32_t* As = reinterpret_cast<const uint32_t*>(sAf + buf * A_TILE_F);
        const uint32_t* Bs = reinterpret_cast<const uint32_t*>(sBf + buf * B_TILE_F);

        #pragma unroll
        for (int ks = 0; ks < 4; ks++) {
            const int k8 = ks * 8;
            uint32_t af[4][4], bf[8][2];
            #pragma unroll
            for (int mi = 0; mi < 4; mi++) {
                const int r0 = wm + mi * 16 + g;
                af[mi][0] = As[r0 * SROW + k8 + t];
                af[mi][1] = As[(r0 + 8) * SROW + k8 + t];
                af[mi][2] = As[r0 * SROW + k8 + t + 4];
                af[mi][3] = As[(r0 + 8) * SROW + k8 + t + 4];
            }
            #pragma unroll
            for (int ni = 0; ni < 8; ni++) {
                const int n0 = wn + ni * 8 + g;
                bf[ni][0] = Bs[n0 * SROW + k8 + t];
                bf[ni][1] = Bs[n0 * SROW + k8 + t + 4];
            }
            #pragma unroll
            for (int mi = 0; mi < 4; mi++)
                #pragma unroll
                for (int ni = 0; ni < 8; ni++)
                    mma_tf32(acc[mi][ni], af[mi], bf[ni]);
        }
        __syncthreads();
    }

    #pragma unroll
    for (int mi = 0; mi < 4; mi++) {
        const int row0 = bm + wm + mi * 16 + g;
        #pragma unroll
        for (int ni = 0; ni < 8; ni++) {
            const int col = bn + wn + ni * 8 + 2 * t;
            const float2 b2 = *reinterpret_cast<const float2*>(&bias[col]);
            float v0 = acc[mi][ni][0] + b2.x;
            float v1 = acc[mi][ni][1] + b2.y;
            float v2 = acc[mi][ni][2] + b2.x;
            float v3 = acc[mi][ni][3] + b2.y;
            if (relu) {
                v0 = fmaxf(v0, 0.f); v1 = fmaxf(v1, 0.f);
                v2 = fmaxf(v2, 0.f); v3 = fmaxf(v3, 0.f);
            }
            v0 *= scale; v1 *= scale; v2 *= scale; v3 *= scale;
            if (res) {
                const float2 r0 = *reinterpret_cast<const float2*>(
                    &res[(size_t)row0 * N + col]);
                const float2 r1 = *reinterpret_cast<const float2*>(
                    &res[(size_t)(row0 + 8) * N + col]);
                v0 += r0.x; v1 += r0.y; v2 += r1.x; v3 += r1.y;
            }
            if (rnd) {
                v0 = f2tf32f(v0); v1 = f2tf32f(v1);
                v2 = f2tf32f(v2); v3 = f2tf32f(v3);
            }
            float2 o0 = {v0, v1}, o1 = {v2, v3};
            *reinterpret_cast<float2*>(&C[(size_t)row0 * N + col]) = o0;
            *reinterpret_cast<float2*>(&C[(size_t)(row0 + 8) * N + col]) = o1;
        }
    }
}

// ================ Flash attention ================
// grid (NS/128, NB*NH), 256 threads. Q tile 128x64, 16 K/V tiles of 128.
// qkv pre-rounded to tf32 in GMEM -> raw copies into SMEM (Q scaled by exact 0.125).
#define QK_S 68
#define SS_S 132
#define VT_S 133
#define FL_SMEM ((128*QK_S + 128*QK_S + 64*VT_S + 128*SS_S + 3*128) * 4)

__global__ __launch_bounds__(256)
void flash_kernel(const float* __restrict__ qkv,
                  const unsigned char* __restrict__ mask,
                  float* __restrict__ ctx) {
    extern __shared__ float fs[];
    float* Qs  = fs;
    float* Ks  = Qs + 128 * QK_S;
    float* Vt  = Ks + 128 * QK_S;
    float* Ss  = Vt + 64 * VT_S;
    float* m_s = Ss + 128 * SS_S;
    float* l_s = m_s + 128;
    float* f_s = l_s + 128;

    const int tid = threadIdx.x;
    const int wid = tid >> 5, lane = tid & 31;
    const int g = lane >> 2, tq = lane & 3;
    const int bh = blockIdx.y;
    const int b = bh >> 4, h = bh & 15;
    const int s0 = blockIdx.x * 128;

    #pragma unroll
    for (int i = 0; i < 8; i++) {
        const int f = tid + i * 256;
        const int r = f >> 4, d4 = (f & 15) << 2;
        const float4 v4 = *reinterpret_cast<const float4*>(
            &qkv[(size_t)(b * NS + s0 + r) * N3 + h * NDH + d4]);
        float* dst = &Qs[r * QK_S + d4];
        dst[0] = v4.x * 0.125f; dst[1] = v4.y * 0.125f;
        dst[2] = v4.z * 0.125f; dst[3] = v4.w * 0.125f;
    }
    if (tid < 128) { m_s[tid] = -INFINITY; l_s[tid] = 0.f; }

    float acco[8][4];
    #pragma unroll
    for (int ni = 0; ni < 8; ni++)
        #pragma unroll
        for (int j = 0; j < 4; j++) acco[ni][j] = 0.f;

    const int row0 = wid * 16 + g;
    const int row1 = row0 + 8;

    for (int it = 0; it < NS / 128; it++) {
        const int t0 = it * 128;
        __syncthreads();

        #pragma unroll
        for (int i = 0; i < 8; i++) {
            const int f = tid + i * 256;
            const int r = f >> 4, d4 = (f & 15) << 2;
            const float4 kv = *reinterpret_cast<const float4*>(
                &qkv[(size_t)(b * NS + t0 + r) * N3 + ND + h * NDH + d4]);
            float* kd = &Ks[r * QK_S + d4];
            kd[0] = kv.x; kd[1] = kv.y; kd[2] = kv.z; kd[3] = kv.w;
            const float4 vv = *reinterpret_cast<const float4*>(
                &qkv[(size_t)(b * NS + t0 + r) * N3 + 2 * ND + h * NDH + d4]);
            Vt[(d4 + 0) * VT_S + r] = vv.x;
            Vt[(d4 + 1) * VT_S + r] = vv.y;
            Vt[(d4 + 2) * VT_S + r] = vv.z;
            Vt[(d4 + 3) * VT_S + r] = vv.w;
        }
        __syncthreads();

        // ---- S = Q K^T ----
        {
            const uint32_t* Qu = reinterpret_cast<const uint32_t*>(Qs);
            const uint32_t* Ku = reinterpret_cast<const uint32_t*>(Ks);
            const int wm = (wid & 1) * 64;
            const int wn = (wid >> 1) * 32;
            float accs[4][4][4];
            #pragma unroll
            for (int mi = 0; mi < 4; mi++)
                #pragma unroll
                for (int ni = 0; ni < 4; ni++)
                    #pragma unroll
                    for (int j = 0; j < 4; j++) accs[mi][ni][j] = 0.f;

            #pragma unroll
            for (int ks = 0; ks < 8; ks++) {
                const int k8 = ks * 8;
                uint32_t af[4][4], bf[4][2];
                #pragma unroll
                for (int mi = 0; mi < 4; mi++) {
                    const int r0 = wm + mi * 16 + g;
                    af[mi][0] = Qu[r0 * QK_S + k8 + tq];
                    af[mi][1] = Qu[(r0 + 8) * QK_S + k8 + tq];
                    af[mi][2] = Qu[r0 * QK_S + k8 + tq + 4];
                    af[mi][3] = Qu[(r0 + 8) * QK_S + k8 + tq + 4];
                }
                #pragma unroll
                for (int ni = 0; ni < 4; ni++) {
                    const int n0 = wn + ni * 8 + g;
                    bf[ni][0] = Ku[n0 * QK_S + k8 + tq];
                    bf[ni][1] = Ku[n0 * QK_S + k8 + tq + 4];
                }
                #pragma unroll
                for (int mi = 0; mi < 4; mi++)
                    #pragma unroll
                    for (int ni = 0; ni < 4; ni++)
                        mma_tf32(accs[mi][ni], af[mi], bf[ni]);
            }
            #pragma unroll
            for (int mi = 0; mi < 4; mi++) {
                const int r = wm + mi * 16 + g;
                #pragma unroll
                for (int ni = 0; ni < 4; ni++) {
                    const int c = wn + ni * 8 + 2 * tq;
                    float2 s0v = {accs[mi][ni][0], accs[mi][ni][1]};
                    float2 s1v = {accs[mi][ni][2], accs[mi][ni][3]};
                    *reinterpret_cast<float2*>(&Ss[r * SS_S + c]) = s0v;
                    *reinterpret_cast<float2*>(&Ss[(r + 8) * SS_S + c]) = s1v;
                }
            }
        }
        __syncthreads();

        // ---- online softmax; P written as tf32 bits ----
        {
            const int r = tid >> 1, h2 = tid & 1;
            const unsigned char* mrow =
                mask + ((size_t)b * NS + s0 + r) * NS + t0 + h2 * 64;
            float4* prow = reinterpret_cast<float4*>(&Ss[r * SS_S + h2 * 64]);

            float mv = -INFINITY;
            #pragma unroll
            for (int j = 0; j < 16; j++) {
                float4 s4 = prow[j];
                const uchar4 mk = reinterpret_cast<const uchar4*>(mrow)[j];
                s4.x = mk.x ? -1e18f : s4.x;
                s4.y = mk.y ? -1e18f : s4.y;
                s4.z = mk.z ? -1e18f : s4.z;
                s4.w = mk.w ? -1e18f : s4.w;
                mv = fmaxf(mv, fmaxf(fmaxf(s4.x, s4.y), fmaxf(s4.z, s4.w)));
            }
            mv = fmaxf(mv, __shfl_xor_sync(0xffffffffu, mv, 1));
            const float mo = m_s[r];
            const float nm = fmaxf(mo, mv);
            const float fc = __expf(mo - nm);

            float sum = 0.f;
            #pragma unroll
            for (int j = 0; j < 16; j++) {
                float4 s4 = prow[j];
                const uchar4 mk = reinterpret_cast<const uchar4*>(mrow)[j];
                s4.x = __expf((mk.x ? -1e18f : s4.x) - nm);
                s4.y = __expf((mk.y ? -1e18f : s4.y) - nm);
                s4.z = __expf((mk.z ? -1e18f : s4.z) - nm);
                s4.w = __expf((mk.w ? -1e18f : s4.w) - nm);
                sum += s4.x + s4.y + s4.z + s4.w;
                s4.x = f2tf32f(s4.x); s4.y = f2tf32f(s4.y);
                s4.z = f2tf32f(s4.z); s4.w = f2tf32f(s4.w);
                prow[j] = s4;
            }
            sum += __shfl_xor_sync(0xffffffffu, sum, 1);
            if (h2 == 0) {
                l_s[r] = l_s[r] * fc + sum;
                f_s[r] = fc;
                m_s[r] = nm;
            }
        }
        __syncthreads();

        // ---- O = O*fc + P V ----
        {
            const uint32_t* Su = reinterpret_cast<const uint32_t*>(Ss);
            const uint32_t* Vu = reinterpret_cast<const uint32_t*>(Vt);
            const float f0 = f_s[row0];
            const float f1 = f_s[row1];
            #pragma unroll
            for (int ni = 0; ni < 8; ni++) {
                acco[ni][0] *= f0; acco[ni][1] *= f0;
                acco[ni][2] *= f1; acco[ni][3] *= f1;
            }
            #pragma unroll
            for (int ks = 0; ks < 16; ks++) {
                const int k8 = ks * 8;
                uint32_t a[4];
                a[0] = Su[row0 * SS_S + k8 + tq];
                a[1] = Su[row1 * SS_S + k8 + tq];
                a[2] = Su[row0 * SS_S + k8 + tq + 4];
                a[3] = Su[row1 * SS_S + k8 + tq + 4];
                #pragma unroll
                for (int ni = 0; ni < 8; ni++) {
                    const int n0 = ni * 8 + g;
                    uint32_t bf[2];
                    bf[0] = Vu[n0 * VT_S + k8 + tq];
                    bf[1] = Vu[n0 * VT_S + k8 + tq + 4];
                    mma_tf32(acco[ni], a, bf);
                }
            }
        }
    }

    // finalize (round ctx to tf32 — it is only consumed as GEMM A)
    const float inv0 = 1.0f / l_s[row0];
    const float inv1 = 1.0f / l_s[row1];
    #pragma unroll
    for (int ni = 0; ni < 8; ni++) {
        const int col = h * NDH + ni * 8 + 2 * tq;
        float2 o0 = {f2tf32f(acco[ni][0] * inv0), f2tf32f(acco[ni][1] * inv0)};
        float2 o1 = {f2tf32f(acco[ni][2] * inv1), f2tf32f(acco[ni][3] * inv1)};
        *reinterpret_cast<float2*>(
            &ctx[(size_t)(b * NS + s0 + row0) * ND + col]) = o0;
        *reinterpret_cast<float2*>(
            &ctx[(size_t)(b * NS + s0 + row1) * ND + col]) = o1;
    }
}

// ---------------- host launch ----------------
extern "C" void kernel_launch(void* const* d_in, const int* in_sizes, int n_in,
                              void* d_out, int out_size) {
    const float* x   = (const float*)d_in[0];
    const unsigned char* mask = (const unsigned char*)d_in[1];
    const float* Wq  = (const float*)d_in[2];
    const float* bq  = (const float*)d_in[3];
    const float* Wk  = (const float*)d_in[4];
    const float* bk  = (const float*)d_in[5];
    const float* Wv  = (const float*)d_in[6];
    const float* bv  = (const float*)d_in[7];
    const float* Wo  = (const float*)d_in[8];
    const float* bo  = (const float*)d_in[9];
    const float* ln1g = (const float*)d_in[10];
    const float* ln1b = (const float*)d_in[11];
    const float* ln2g = (const float*)d_in[12];
    const float* ln2b = (const float*)d_in[13];
    const float* W1  = (const float*)d_in[14];
    const float* b1  = (const float*)d_in[15];
    const float* W2  = (const float*)d_in[16];
    const float* b2  = (const float*)d_in[17];
    float* out = (float*)d_out;

    float *h, *ctx, *ffn, *qkv, *wqkv, *wo, *w1, *w2, *bqkv;
    cudaGetSymbolAddress((void**)&h,    g_h);
    cudaGetSymbolAddress((void**)&ctx,  g_ctx);
    cudaGetSymbolAddress((void**)&ffn,  g_ffn);
    cudaGetSymbolAddress((void**)&qkv,  g_qkv);
    cudaGetSymbolAddress((void**)&wqkv, g_wqkv);
    cudaGetSymbolAddress((void**)&wo,   g_wo);
    cudaGetSymbolAddress((void**)&w1,   g_w1);
    cudaGetSymbolAddress((void**)&w2,   g_w2);
    cudaGetSymbolAddress((void**)&bqkv, g_bqkv);

    cudaFuncSetAttribute(mma_gemm, cudaFuncAttributeMaxDynamicSharedMemorySize,
                         GEMM_SMEM);
    cudaFuncSetAttribute(flash_kernel, cudaFuncAttributeMaxDynamicSharedMemorySize,
                         FL_SMEM);

    // launch order: 0 prepB, 1 prepA, 2 prepC, 3 ln1, 4 qkv, 5 flash, ...
    prepB_kernel<<<dim3(128, 32, 2), 256>>>(Wo, wo, W1, w1);
    prepA_kernel<<<dim3(32, 32, 3), 256>>>(Wq, Wk, Wv, wqkv);
    prepC_kernel<<<dim3(32, 128, 2), 256>>>(W2, w2, bq, bk, bv, bqkv);
    ln_kernel<<<NM, 256>>>(x, ln1g, ln1b, h);

    // fused QKV projection (output rounded to tf32; scale applied in flash)
    mma_gemm<<<dim3(N3/256, NM/128), 256, GEMM_SMEM>>>(N3, ND, h, wqkv, bqkv,
                                                       nullptr, qkv, 1.0f, 0, 1);
    // flash attention -> ctx (tf32-rounded)
    flash_kernel<<<dim3(NS/128, NB*NH), 256, FL_SMEM>>>(qkv, mask, ctx);
    // x1 = x + ctx @ Wo + bo -> out (fp32, final/residual)
    mma_gemm<<<dim3(ND/256, NM/128), 256, GEMM_SMEM>>>(ND, ND, ctx, wo, bo, x, out,
                                                       1.0f, 0, 0);
    // LN2 (output tf32-rounded)
    ln_kernel<<<NM, 256>>>(out, ln2g, ln2b, h);
    // ffn = relu(h @ W1 + b1), rounded to tf32
    mma_gemm<<<dim3(NF/256, NM/128), 256, GEMM_SMEM>>>(NF, ND, h, w1, b1, nullptr,
                                                       ffn, 1.0f, 1, 1);
    // out = x1 + ffn @ W2 + b2 (fp32 final)
    mma_gemm<<<dim3(ND/256, NM/128), 256, GEMM_SMEM>>>(ND, NF, ffn, w2, b2, out, out,
                                                       1.0f, 0, 0);
}